// round 12
// baseline (speedup 1.0000x reference)
#include <cuda_runtime.h>
#include <cuda_bf16.h>
#include <math.h>
#include <stdint.h>

#define BB 2
#define NNTOK 2048
#define DD 1024
#define HH 16
#define HDIM 64
#define BN (BB*NNTOK)
#define RT 32

// ---------------- scratch (device globals) ----------------------------------
__device__ __nv_bfloat16 g_xhi[BN*DD], g_xlo[BN*DD];
__device__ __nv_bfloat16 g_nhi[BN*DD], g_nlo[BN*DD];
__device__ __nv_bfloat16 g_wqhi[DD*DD], g_wqlo[DD*DD];
__device__ __nv_bfloat16 g_wkhi[DD*DD], g_wklo[DD*DD];
__device__ __nv_bfloat16 g_wvhi[DD*DD], g_wvlo[DD*DD];
__device__ __nv_bfloat16 g_wohi[DD*DD], g_wolo[DD*DD];
__device__ __nv_bfloat16 g_wshi[128*DD], g_wslo[128*DD];
__device__ float g_q [BN*DD];
__device__ float g_k [BN*DD];
__device__ float g_v [BN*DD];
__device__ float g_o [BN*DD];
__device__ float g_f [BN*HH];
__device__ float g_g [BN*HH];
__device__ float g_g1[BN*HDIM];
__device__ float g_dummy[32];

__device__ __forceinline__ float sigmoidf_(float x) { return 1.f / (1.f + expf(-x)); }

__device__ __forceinline__ uint32_t s2u(const void* p) {
    uint32_t a;
    asm("{ .reg .u64 t; cvta.to.shared.u64 t, %1; cvt.u32.u64 %0, t; }" : "=r"(a) : "l"(p));
    return a;
}
__device__ __forceinline__ void cp16(uint32_t dst, const void* src) {
    asm volatile("cp.async.cg.shared.global [%0], [%1], 16;" :: "r"(dst), "l"(src) : "memory");
}
__device__ __forceinline__ void cp4(uint32_t dst, const void* src) {
    asm volatile("cp.async.ca.shared.global [%0], [%1], 4;" :: "r"(dst), "l"(src) : "memory");
}
__device__ __forceinline__ void ldm4(uint32_t* r, uint32_t addr) {
    asm volatile("ldmatrix.sync.aligned.m8n8.x4.shared.b16 {%0,%1,%2,%3}, [%4];"
        : "=r"(r[0]), "=r"(r[1]), "=r"(r[2]), "=r"(r[3]) : "r"(addr));
}
__device__ __forceinline__ void mma16816(float* d, const uint32_t* a, const uint32_t* b) {
    asm volatile("mma.sync.aligned.m16n8k16.row.col.f32.bf16.bf16.f32 "
        "{%0,%1,%2,%3}, {%4,%5,%6,%7}, {%8,%9}, {%0,%1,%2,%3};"
        : "+f"(d[0]), "+f"(d[1]), "+f"(d[2]), "+f"(d[3])
        : "r"(a[0]), "r"(a[1]), "r"(a[2]), "r"(a[3]), "r"(b[0]), "r"(b[1]));
}

// ---------------- merged prep ------------------------------------------------
__global__ __launch_bounds__(256) void prep_kernel(
    const float* __restrict__ x,
    const float* __restrict__ Wq, const float* __restrict__ Wk,
    const float* __restrict__ Wv, const float* __restrict__ Wo,
    const float* __restrict__ Wg, const float* __restrict__ Wf,
    const float* __restrict__ Wg1)
{
    __shared__ float ts[32][33];
    const int bid = blockIdx.x, tid = threadIdx.x;
    if (bid < 16384) {
        int i = bid * 256 + tid;
        float v = x[i];
        __nv_bfloat16 h = __float2bfloat16(v);
        g_xhi[i] = h;
        g_xlo[i] = __float2bfloat16(v - __bfloat162float(h));
    } else if (bid < 16384 + 4096) {
        int t = bid - 16384;
        int z = t >> 10, rem = t & 1023;
        int bx = rem & 31, by = rem >> 5;
        const float* W; __nv_bfloat16 *hi, *lo;
        switch (z) {
            case 0:  W = Wq; hi = g_wqhi; lo = g_wqlo; break;
            case 1:  W = Wk; hi = g_wkhi; lo = g_wklo; break;
            case 2:  W = Wv; hi = g_wvhi; lo = g_wvlo; break;
            default: W = Wo; hi = g_wohi; lo = g_wolo; break;
        }
        const int r = tid >> 5, c = tid & 31;
#pragma unroll
        for (int i = 0; i < 4; i++)
            ts[r + 8*i][c] = W[(size_t)(by*32 + r + 8*i) * DD + bx*32 + c];
        __syncthreads();
#pragma unroll
        for (int i = 0; i < 4; i++) {
            int n = bx*32 + r + 8*i, k = by*32 + c;
            float v = ts[c][r + 8*i];
            __nv_bfloat16 h = __float2bfloat16(v);
            hi[(size_t)n*DD + k] = h;
            lo[(size_t)n*DD + k] = __float2bfloat16(v - __bfloat162float(h));
        }
    } else {
        int n = bid - (16384 + 4096);
        for (int k = tid; k < DD; k += 256) {
            float v = (n < 16) ? Wg[(size_t)k*16 + n] : (n < 32) ? Wf[(size_t)k*16 + n - 16]
                    : (n < 96) ? Wg1[(size_t)k*64 + n - 32] : 0.f;
            __nv_bfloat16 h = __float2bfloat16(v);
            g_wshi[(size_t)n*DD + k] = h;
            g_wslo[(size_t)n*DD + k] = __float2bfloat16(v - __bfloat162float(h));
        }
    }
}

// ---------------- bf16 split GEMM core ---------------------------------------
#define PITCH 80
#define ABUF (128*PITCH)
#define STG (2*ABUF)
#define GSMEM (4*STG)
__device__ __forceinline__ void gemm_core(
    const __nv_bfloat16* __restrict__ Ahi, const __nv_bfloat16* __restrict__ Alo,
    const __nv_bfloat16* __restrict__ Bhi, const __nv_bfloat16* __restrict__ Blo,
    float* __restrict__ C, int md, int m0, int n0)
{
    extern __shared__ __align__(16) char sm[];
    const uint32_t sb = s2u(sm);
    const int tid = threadIdx.x, wid = tid >> 5, lane = tid & 31;
    const int wm = wid >> 2, wn = wid & 3;

    float acc[4][4][4];
#pragma unroll
    for (int i = 0; i < 4; i++)
#pragma unroll
        for (int j = 0; j < 4; j++)
#pragma unroll
            for (int l = 0; l < 4; l++) acc[i][j][l] = 0.f;

    auto load_chunk = [&](int kf) {
        const int seg = kf >> 5;
        const __nv_bfloat16* Aa = (seg == 1) ? Alo : Ahi;
        const __nv_bfloat16* Ba = (seg == 2) ? Blo : Bhi;
        const int kl = (kf & 31) * 32;
        const uint32_t base = sb + (uint32_t)(kf & 3) * STG;
#pragma unroll
        for (int i = 0; i < 2; i++) {
            int idx = tid + i * 256;
            int row = idx >> 2, q = idx & 3;
            cp16(base + row * PITCH + q * 16, Aa + (size_t)(m0 + row) * DD + kl + q * 8);
            cp16(base + ABUF + row * PITCH + q * 16, Ba + (size_t)(n0 + row) * DD + kl + q * 8);
        }
        asm volatile("cp.async.commit_group;" ::: "memory");
    };

    load_chunk(0); load_chunk(1); load_chunk(2);

    const int la = lane & 15, lb8 = (lane >> 4) * 16;
    const int rb_row = ((lane >> 4) & 1) * 8 + (lane & 7);
    const int rb_col = ((lane >> 3) & 1) * 16;
    uint32_t offa[4], offb[2];
#pragma unroll
    for (int mi = 0; mi < 4; mi++) offa[mi] = (uint32_t)((wm*64 + mi*16 + la) * PITCH + lb8);
#pragma unroll
    for (int nj = 0; nj < 2; nj++) offb[nj] = (uint32_t)((wn*32 + nj*16 + rb_row) * PITCH + rb_col);

    for (int kc = 0; kc < 96; kc++) {
        asm volatile("cp.async.wait_group 2;" ::: "memory");
        __syncthreads();

        const uint32_t As = sb + (uint32_t)(kc & 3) * STG;
        const uint32_t Bs = As + ABUF;
        uint32_t a[2][4][4], b[2][4][2];
#pragma unroll
        for (int ks = 0; ks < 2; ks++) {
#pragma unroll
            for (int mi = 0; mi < 4; mi++) ldm4(a[ks][mi], As + offa[mi] + ks*32);
#pragma unroll
            for (int nj = 0; nj < 2; nj++) {
                uint32_t t[4];
                ldm4(t, Bs + offb[nj] + ks*32);
                b[ks][nj*2][0] = t[0]; b[ks][nj*2][1] = t[1];
                b[ks][nj*2+1][0] = t[2]; b[ks][nj*2+1][1] = t[3];
            }
        }
        if (kc + 3 < 96) load_chunk(kc + 3);
        else asm volatile("cp.async.commit_group;" ::: "memory");
#pragma unroll
        for (int ks = 0; ks < 2; ks++)
#pragma unroll
            for (int mi = 0; mi < 4; mi++)
#pragma unroll
                for (int ni = 0; ni < 4; ni++)
                    mma16816(acc[mi][ni], a[ks][mi], b[ks][ni]);
    }

    const int r_lo = lane >> 2, c_lo = (lane & 3) * 2;

    if (md == 1 || md == 2) {
#pragma unroll
        for (int mi = 0; mi < 4; mi++)
#pragma unroll
            for (int ni = 0; ni < 4; ni++)
#pragma unroll
                for (int l = 0; l < 4; l++) {
                    float z = acc[mi][ni][l];
                    acc[mi][ni][l] = z * sigmoidf_(z);
                }
    }

    float inv[4][2];
#pragma unroll
    for (int mi = 0; mi < 4; mi++) { inv[mi][0] = 1.f; inv[mi][1] = 1.f; }

    if (md == 2) {
        __syncthreads();
        float* red = (float*)sm;
#pragma unroll
        for (int mi = 0; mi < 4; mi++) {
#pragma unroll
            for (int half = 0; half < 2; half++) {
                float ss = 0.f;
#pragma unroll
                for (int ni = 0; ni < 4; ni++) {
                    float v0 = acc[mi][ni][half*2], v1 = acc[mi][ni][half*2+1];
                    ss = fmaf(v0, v0, fmaf(v1, v1, ss));
                }
                ss += __shfl_xor_sync(0xffffffffu, ss, 1);
                ss += __shfl_xor_sync(0xffffffffu, ss, 2);
                if ((lane & 3) == 0) {
                    int rloc = wm*64 + mi*16 + r_lo + half*8;
                    red[rloc*4 + wn] = ss;
                }
            }
        }
        __syncthreads();
#pragma unroll
        for (int mi = 0; mi < 4; mi++)
#pragma unroll
            for (int half = 0; half < 2; half++) {
                int rloc = wm*64 + mi*16 + r_lo + half*8;
                float tot = red[rloc*4 + wn] + red[rloc*4 + (wn^1)];
                inv[mi][half] = 1.f / fmaxf(sqrtf(tot), 1e-12f);
            }
    }

#pragma unroll
    for (int mi = 0; mi < 4; mi++) {
#pragma unroll
        for (int ni = 0; ni < 4; ni++) {
#pragma unroll
            for (int half = 0; half < 2; half++) {
                int row = m0 + wm*64 + mi*16 + r_lo + half*8;
                int col = wn*32 + ni*8 + c_lo;
                float v0 = acc[mi][ni][half*2], v1 = acc[mi][ni][half*2 + 1];
                if (md == 2) { v0 *= inv[mi][half]; v1 *= inv[mi][half]; }
                if (md == 3) {
#pragma unroll
                    for (int e = 0; e < 2; e++) {
                        int cc = col + e;
                        float z = e ? v1 : v0;
                        if (cc < 16)      g_g [(size_t)row*HH + cc]        = sigmoidf_(z);
                        else if (cc < 32) g_f [(size_t)row*HH + cc - 16]   = sigmoidf_(z);
                        else if (cc < 96) g_g1[(size_t)row*HDIM + cc - 32] = z;
                    }
                } else {
                    *(float2*)(C + (size_t)row * DD + n0 + col) = make_float2(v0, v1);
                }
            }
        }
    }
}

__global__ __launch_bounds__(256, 2) void gemm_qkv() {
    const int tn = blockIdx.x, m0 = blockIdx.y * 128;
    if (tn < 8)        gemm_core(g_xhi, g_xlo, g_wqhi, g_wqlo, g_q, 1, m0, tn*128);
    else if (tn == 8)  gemm_core(g_xhi, g_xlo, g_wshi, g_wslo, g_q, 3, m0, 0);
    else if (tn < 17)  gemm_core(g_xhi, g_xlo, g_wkhi, g_wklo, g_k, 2, m0, (tn-9)*128);
    else               gemm_core(g_xhi, g_xlo, g_wvhi, g_wvlo, g_v, 1, m0, (tn-17)*128);
}
__global__ __launch_bounds__(256, 2) void gemm_out(float* __restrict__ C) {
    gemm_core(g_nhi, g_nlo, g_wohi, g_wolo, C, 0, blockIdx.y * 128, blockIdx.x * 128);
}

__global__ void dummy_kernel() { g_dummy[threadIdx.x] = 0.f; }

// ---------------- recurrence: TWO chains interleaved per warp ----------------
// 64 blocks = (bh-pair) x col-quarter(16). Each warp: 4 cols x 8 segs for BOTH chains.
// smem float offsets:
#define R_KS 0          /* [chain2][buf2][32][64] = 8192 */
#define R_QS 8192       /* 8192 */
#define R_VS 16384      /* [2][2][32][16] = 2048 */
#define R_FS 18432      /* [2][2][32] = 128 */
#define R_GS 18560      /* 128 */
#define R_PO 18688      /* [2][32][136] = 8704 */
#define RSMEM_BYTES ((18688 + 8704) * 4)
__global__ __launch_bounds__(128) void recur_kernel() {
    extern __shared__ float rs[];
    const int blk = blockIdx.x;            // 0..63
    const int bhp = blk >> 2, qtr = blk & 3;
    const int tid = threadIdx.x;
    const int w = tid >> 5, lane = tid & 31;
    const int col_local = w*4 + (lane & 3);
    const int seg = lane >> 2;
    const int r0 = seg * 8;

    const int bh0 = bhp*2, bh1 = bhp*2 + 1;
    const size_t basev0 = (size_t)(bh0 >> 4)*NNTOK*DD + (bh0 & 15)*HDIM;
    const size_t basev1 = (size_t)(bh1 >> 4)*NNTOK*DD + (bh1 & 15)*HDIM;
    const size_t basef0 = (size_t)(bh0 >> 4)*NNTOK*HH + (bh0 & 15);
    const size_t basef1 = (size_t)(bh1 >> 4)*NNTOK*HH + (bh1 & 15);

    auto stage = [&](int tile) {
        const int buf = tile & 1;
        const int t0 = tile * RT;
#pragma unroll
        for (int c = 0; c < 2; c++) {
            const size_t bv = c ? basev1 : basev0;
            const size_t bf = c ? basef1 : basef0;
            const float* kg = g_k + bv + (size_t)t0 * DD;
            const float* qg = g_q + bv + (size_t)t0 * DD;
            const float* vg = g_v + bv + (size_t)t0 * DD + qtr*16;
#pragma unroll
            for (int p = 0; p < 4; p++) {
                int idx = tid + p*128;
                int r = idx >> 4, i = (idx & 15) * 4;
                cp16(s2u(rs + R_KS + c*4096 + buf*2048 + r*64 + i), kg + (size_t)r*DD + i);
                cp16(s2u(rs + R_QS + c*4096 + buf*2048 + r*64 + i), qg + (size_t)r*DD + i);
            }
            {
                int r = tid >> 2, i = (tid & 3) * 4;
                cp16(s2u(rs + R_VS + c*1024 + buf*512 + r*16 + i), vg + (size_t)r*DD + i);
            }
            if (tid < RT)        cp4(s2u(rs + R_FS + c*64 + buf*32 + tid),      g_f + bf + (size_t)(t0+tid)*HH);
            else if (tid < 2*RT) cp4(s2u(rs + R_GS + c*64 + buf*32 + (tid-RT)), g_g + bf + (size_t)(t0+tid-RT)*HH);
        }
        asm volatile("cp.async.commit_group;" ::: "memory");
    };

    float S0[8], S1[8];
#pragma unroll
    for (int i = 0; i < 8; i++) { S0[i] = 0.f; S1[i] = 0.f; }

    stage(0);
    const int NT = NNTOK / RT;
    for (int tile = 0; tile < NT; tile++) {
        const int buf = tile & 1;
        __syncthreads();
        if (tile + 1 < NT) {
            stage(tile + 1);
            asm volatile("cp.async.wait_group 1;" ::: "memory");
        } else {
            asm volatile("cp.async.wait_group 0;" ::: "memory");
        }
        __syncthreads();

        const float* kb0 = rs + R_KS + buf*2048 + r0;
        const float* qb0 = rs + R_QS + buf*2048 + r0;
        const float* vb0 = rs + R_VS + buf*512 + col_local;
        const float* fb0 = rs + R_FS + buf*32;
        const float* gb0 = rs + R_GS + buf*32;
        const float* kb1 = kb0 + 4096;
        const float* qb1 = qb0 + 4096;
        const float* vb1 = vb0 + 1024;
        const float* fb1 = fb0 + 64;
        const float* gb1 = gb0 + 64;

        // prefetch step 0 for both chains
        float k0[8], q0[8], v0, f0, g0, k1[8], q1[8], v1, f1, g1;
        *(float4*)(k0)   = *(const float4*)(kb0);
        *(float4*)(k0+4) = *(const float4*)(kb0+4);
        *(float4*)(q0)   = *(const float4*)(qb0);
        *(float4*)(q0+4) = *(const float4*)(qb0+4);
        v0 = vb0[0]; f0 = fb0[0]; g0 = gb0[0];
        *(float4*)(k1)   = *(const float4*)(kb1);
        *(float4*)(k1+4) = *(const float4*)(kb1+4);
        *(float4*)(q1)   = *(const float4*)(qb1);
        *(float4*)(q1+4) = *(const float4*)(qb1+4);
        v1 = vb1[0]; f1 = fb1[0]; g1 = gb1[0];

#pragma unroll
        for (int tt = 0; tt < RT; tt++) {
            const int nx = (tt + 1 < RT) ? (tt + 1) : (RT - 1);
            float k0B[8], q0B[8], v0B, f0B, g0B, k1B[8], q1B[8], v1B, f1B, g1B;
            *(float4*)(k0B)   = *(const float4*)(kb0 + nx*64);
            *(float4*)(k0B+4) = *(const float4*)(kb0 + nx*64 + 4);
            *(float4*)(q0B)   = *(const float4*)(qb0 + nx*64);
            *(float4*)(q0B+4) = *(const float4*)(qb0 + nx*64 + 4);
            v0B = vb0[nx*16]; f0B = fb0[nx]; g0B = gb0[nx];
            *(float4*)(k1B)   = *(const float4*)(kb1 + nx*64);
            *(float4*)(k1B+4) = *(const float4*)(kb1 + nx*64 + 4);
            *(float4*)(q1B)   = *(const float4*)(qb1 + nx*64);
            *(float4*)(q1B+4) = *(const float4*)(qb1 + nx*64 + 4);
            v1B = vb1[nx*16]; f1B = fb1[nx]; g1B = gb1[nx];

            // chain 0 d-reduction
            const float cc0 = -g0 * f0 * f0;
            float p00 = 0.f, p01 = 0.f;
#pragma unroll
            for (int i = 0; i < 4; i++) {
                p00 = fmaf(k0[i],   S0[i],   p00);
                p01 = fmaf(k0[i+4], S0[i+4], p01);
            }
            float d0 = p00 + p01;
            d0 += __shfl_xor_sync(0xffffffffu, d0, 4);
            d0 += __shfl_xor_sync(0xffffffffu, d0, 8);
            d0 += __shfl_xor_sync(0xffffffffu, d0, 16);

            // chain 1 d-reduction (independent — fills chain 0's shfl shadow)
            const float cc1 = -g1 * f1 * f1;
            float p10 = 0.f, p11 = 0.f;
#pragma unroll
            for (int i = 0; i < 4; i++) {
                p10 = fmaf(k1[i],   S1[i],   p10);
                p11 = fmaf(k1[i+4], S1[i+4], p11);
            }
            float d1 = p10 + p11;
            d1 += __shfl_xor_sync(0xffffffffu, d1, 4);
            d1 += __shfl_xor_sync(0xffffffffu, d1, 8);
            d1 += __shfl_xor_sync(0xffffffffu, d1, 16);

            // chain 0 update
            const float u0 = fmaf(cc0, d0, v0);
            float o00 = 0.f, o01 = 0.f;
#pragma unroll
            for (int i = 0; i < 4; i++) {
                S0[i]   = fmaf(f0, S0[i],   k0[i]   * u0); o00 = fmaf(q0[i],   S0[i],   o00);
                S0[i+4] = fmaf(f0, S0[i+4], k0[i+4] * u0); o01 = fmaf(q0[i+4], S0[i+4], o01);
            }
            rs[R_PO + tt*136 + seg*17 + col_local] = o00 + o01;

            // chain 1 update
            const float u1 = fmaf(cc1, d1, v1);
            float o10 = 0.f, o11 = 0.f;
#pragma unroll
            for (int i = 0; i < 4; i++) {
                S1[i]   = fmaf(f1, S1[i],   k1[i]   * u1); o10 = fmaf(q1[i],   S1[i],   o10);
                S1[i+4] = fmaf(f1, S1[i+4], k1[i+4] * u1); o11 = fmaf(q1[i+4], S1[i+4], o11);
            }
            rs[R_PO + 4352 + tt*136 + seg*17 + col_local] = o10 + o11;

#pragma unroll
            for (int i = 0; i < 8; i++) {
                k0[i] = k0B[i]; q0[i] = q0B[i];
                k1[i] = k1B[i]; q1[i] = q1B[i];
            }
            v0 = v0B; f0 = f0B; g0 = g0B;
            v1 = v1B; f1 = f1B; g1 = g1B;
        }
        __syncthreads();

        // bulk o-reduction + coalesced store, both chains (8 reps total)
        {
            const int colr = tid & 15, tg = tid >> 4;
#pragma unroll
            for (int rep = 0; rep < 4; rep++) {
                int t = tg + rep*8;
                float s0 = 0.f, s1 = 0.f;
#pragma unroll
                for (int sg = 0; sg < 8; sg++) {
                    s0 += rs[R_PO + t*136 + sg*17 + colr];
                    s1 += rs[R_PO + 4352 + t*136 + sg*17 + colr];
                }
                g_o[basev0 + (size_t)(tile*RT + t)*DD + qtr*16 + colr] = s0;
                g_o[basev1 + (size_t)(tile*RT + t)*DD + qtr*16 + colr] = s1;
            }
        }
    }
}

// -------- gate + LayerNorm -> bf16 hi/lo split (vectorized g1 loads) ---------
__global__ __launch_bounds__(256) void gate_ln_kernel(const float* __restrict__ Wg2,
                                                      const float* __restrict__ nw) {
    __shared__ float g1s[8 * 64];
    __shared__ float rb[8 * 1024];
    const int row0 = blockIdx.x * 8;
    const int tid = threadIdx.x;
    for (int i = tid; i < 512; i += 256) g1s[i] = g_g1[(size_t)row0 * 64 + i];
    __syncthreads();

    float a[8][4];
#pragma unroll
    for (int r = 0; r < 8; r++)
#pragma unroll
        for (int ch = 0; ch < 4; ch++) a[r][ch] = 0.f;

    for (int k4 = 0; k4 < 64; k4 += 4) {
        float4 gr[8];
#pragma unroll
        for (int r = 0; r < 8; r++) gr[r] = *(const float4*)&g1s[r*64 + k4];
#pragma unroll
        for (int ch = 0; ch < 4; ch++) {
            const int c = tid + ch * 256;
            float w0 = Wg2[(size_t)(k4+0)*DD + c];
            float w1 = Wg2[(size_t)(k4+1)*DD + c];
            float w2 = Wg2[(size_t)(k4+2)*DD + c];
            float w3 = Wg2[(size_t)(k4+3)*DD + c];
#pragma unroll
            for (int r = 0; r < 8; r++) {
                float t = fmaf(gr[r].x, w0, fmaf(gr[r].y, w1, fmaf(gr[r].z, w2, gr[r].w * w3)));
                a[r][ch] += t;
            }
        }
    }
#pragma unroll
    for (int ch = 0; ch < 4; ch++) {
        const int c = tid + ch * 256;
#pragma unroll
        for (int r = 0; r < 8; r++)
            rb[r * 1024 + c] = g_o[(size_t)(row0 + r) * DD + c] * sigmoidf_(a[r][ch]);
    }
    __syncthreads();
    const int wr = tid >> 5, ln = tid & 31;
    float s = 0.f, s2 = 0.f;
#pragma unroll 8
    for (int i = 0; i < 32; i++) {
        float v = rb[wr * 1024 + ln + 32 * i];
        s += v; s2 = fmaf(v, v, s2);
    }
#pragma unroll
    for (int o = 16; o; o >>= 1) {
        s  += __shfl_xor_sync(0xffffffffu, s,  o);
        s2 += __shfl_xor_sync(0xffffffffu, s2, o);
    }
    const float mu = s * (1.f / 1024.f);
    const float rstd = rsqrtf(s2 * (1.f / 1024.f) - mu * mu + 1e-5f);
#pragma unroll 8
    for (int i = 0; i < 32; i++) {
        int c = ln + 32 * i;
        float v = (rb[wr * 1024 + c] - mu) * rstd * nw[c];
        __nv_bfloat16 hi = __float2bfloat16(v);
        size_t idx = (size_t)(row0 + wr) * DD + c;
        g_nhi[idx] = hi;
        g_nlo[idx] = __float2bfloat16(v - __bfloat162float(hi));
    }
}

// -----------------------------------------------------------------------------
extern "C" void kernel_launch(void* const* d_in, const int* in_sizes, int n_in,
                              void* d_out, int out_size) {
    const float* x      = (const float*)d_in[0];
    const float* Wq     = (const float*)d_in[1];
    const float* Wk     = (const float*)d_in[2];
    const float* Wv     = (const float*)d_in[3];
    const float* Wgamma = (const float*)d_in[4];
    const float* Wf     = (const float*)d_in[5];
    const float* Wg1    = (const float*)d_in[6];
    const float* Wg2    = (const float*)d_in[7];
    const float* Wo     = (const float*)d_in[8];
    const float* norm_w = (const float*)d_in[9];
    float* out = (float*)d_out;

    cudaFuncSetAttribute(gemm_qkv, cudaFuncAttributeMaxDynamicSharedMemorySize, GSMEM);
    cudaFuncSetAttribute(gemm_out, cudaFuncAttributeMaxDynamicSharedMemorySize, GSMEM);
    cudaFuncSetAttribute(recur_kernel, cudaFuncAttributeMaxDynamicSharedMemorySize, RSMEM_BYTES);

    prep_kernel<<<16384 + 4096 + 128, 256>>>(x, Wq, Wk, Wv, Wo, Wgamma, Wf, Wg1);  // 0
    gemm_qkv<<<dim3(25, 32), 256, GSMEM>>>();                                       // 1
    dummy_kernel<<<1, 32>>>();                                                      // 2
    recur_kernel<<<64, 128, RSMEM_BYTES>>>();                                       // 3 <- profiled
    gate_ln_kernel<<<BN/8, 256>>>(Wg2, norm_w);                                     // 4
    gemm_out<<<dim3(8, 32), 256, GSMEM>>>(out);                                     // 5
}

// round 13
// speedup vs baseline: 1.2372x; 1.2372x over previous
#include <cuda_runtime.h>
#include <cuda_bf16.h>
#include <math.h>
#include <stdint.h>

#define BB 2
#define NNTOK 2048
#define DD 1024
#define HH 16
#define HDIM 64
#define BN (BB*NNTOK)
#define RT 32

// ---------------- scratch (device globals) ----------------------------------
__device__ __nv_bfloat16 g_xhi[BN*DD], g_xlo[BN*DD];
__device__ __nv_bfloat16 g_nhi[BN*DD], g_nlo[BN*DD];
__device__ __nv_bfloat16 g_wqhi[DD*DD], g_wqlo[DD*DD];
__device__ __nv_bfloat16 g_wkhi[DD*DD], g_wklo[DD*DD];
__device__ __nv_bfloat16 g_wvhi[DD*DD], g_wvlo[DD*DD];
__device__ __nv_bfloat16 g_wohi[DD*DD], g_wolo[DD*DD];
__device__ __nv_bfloat16 g_wshi[128*DD], g_wslo[128*DD];
__device__ float g_q [BN*DD];
__device__ float g_k [BN*DD];
__device__ float g_v [BN*DD];
__device__ float g_o [BN*DD];
__device__ float g_f [BN*HH];
__device__ float g_g [BN*HH];
__device__ float g_g1[BN*HDIM];
__device__ float g_dummy[32];

__device__ __forceinline__ float sigmoidf_(float x) { return 1.f / (1.f + expf(-x)); }

__device__ __forceinline__ uint32_t s2u(const void* p) {
    uint32_t a;
    asm("{ .reg .u64 t; cvta.to.shared.u64 t, %1; cvt.u32.u64 %0, t; }" : "=r"(a) : "l"(p));
    return a;
}
__device__ __forceinline__ void cp16(uint32_t dst, const void* src) {
    asm volatile("cp.async.cg.shared.global [%0], [%1], 16;" :: "r"(dst), "l"(src) : "memory");
}
__device__ __forceinline__ void cp4(uint32_t dst, const void* src) {
    asm volatile("cp.async.ca.shared.global [%0], [%1], 4;" :: "r"(dst), "l"(src) : "memory");
}
__device__ __forceinline__ void ldm4(uint32_t* r, uint32_t addr) {
    asm volatile("ldmatrix.sync.aligned.m8n8.x4.shared.b16 {%0,%1,%2,%3}, [%4];"
        : "=r"(r[0]), "=r"(r[1]), "=r"(r[2]), "=r"(r[3]) : "r"(addr));
}
__device__ __forceinline__ void mma16816(float* d, const uint32_t* a, const uint32_t* b) {
    asm volatile("mma.sync.aligned.m16n8k16.row.col.f32.bf16.bf16.f32 "
        "{%0,%1,%2,%3}, {%4,%5,%6,%7}, {%8,%9}, {%0,%1,%2,%3};"
        : "+f"(d[0]), "+f"(d[1]), "+f"(d[2]), "+f"(d[3])
        : "r"(a[0]), "r"(a[1]), "r"(a[2]), "r"(a[3]), "r"(b[0]), "r"(b[1]));
}

// ---------------- merged prep ------------------------------------------------
__global__ __launch_bounds__(256) void prep_kernel(
    const float* __restrict__ x,
    const float* __restrict__ Wq, const float* __restrict__ Wk,
    const float* __restrict__ Wv, const float* __restrict__ Wo,
    const float* __restrict__ Wg, const float* __restrict__ Wf,
    const float* __restrict__ Wg1)
{
    __shared__ float ts[32][33];
    const int bid = blockIdx.x, tid = threadIdx.x;
    if (bid < 16384) {
        int i = bid * 256 + tid;
        float v = x[i];
        __nv_bfloat16 h = __float2bfloat16(v);
        g_xhi[i] = h;
        g_xlo[i] = __float2bfloat16(v - __bfloat162float(h));
    } else if (bid < 16384 + 4096) {
        int t = bid - 16384;
        int z = t >> 10, rem = t & 1023;
        int bx = rem & 31, by = rem >> 5;
        const float* W; __nv_bfloat16 *hi, *lo;
        switch (z) {
            case 0:  W = Wq; hi = g_wqhi; lo = g_wqlo; break;
            case 1:  W = Wk; hi = g_wkhi; lo = g_wklo; break;
            case 2:  W = Wv; hi = g_wvhi; lo = g_wvlo; break;
            default: W = Wo; hi = g_wohi; lo = g_wolo; break;
        }
        const int r = tid >> 5, c = tid & 31;
#pragma unroll
        for (int i = 0; i < 4; i++)
            ts[r + 8*i][c] = W[(size_t)(by*32 + r + 8*i) * DD + bx*32 + c];
        __syncthreads();
#pragma unroll
        for (int i = 0; i < 4; i++) {
            int n = bx*32 + r + 8*i, k = by*32 + c;
            float v = ts[c][r + 8*i];
            __nv_bfloat16 h = __float2bfloat16(v);
            hi[(size_t)n*DD + k] = h;
            lo[(size_t)n*DD + k] = __float2bfloat16(v - __bfloat162float(h));
        }
    } else {
        int n = bid - (16384 + 4096);
        for (int k = tid; k < DD; k += 256) {
            float v = (n < 16) ? Wg[(size_t)k*16 + n] : (n < 32) ? Wf[(size_t)k*16 + n - 16]
                    : (n < 96) ? Wg1[(size_t)k*64 + n - 32] : 0.f;
            __nv_bfloat16 h = __float2bfloat16(v);
            g_wshi[(size_t)n*DD + k] = h;
            g_wslo[(size_t)n*DD + k] = __float2bfloat16(v - __bfloat162float(h));
        }
    }
}

// ---------------- bf16 split GEMM core: 4 warps, warp tile 64x64 -------------
#define PITCH 80
#define ABUF (128*PITCH)
#define STG (2*ABUF)
#define GSMEM (4*STG)
__device__ __forceinline__ void gemm_core(
    const __nv_bfloat16* __restrict__ Ahi, const __nv_bfloat16* __restrict__ Alo,
    const __nv_bfloat16* __restrict__ Bhi, const __nv_bfloat16* __restrict__ Blo,
    float* __restrict__ C, int md, int m0, int n0)
{
    extern __shared__ __align__(16) char sm[];
    const uint32_t sb = s2u(sm);
    const int tid = threadIdx.x, wid = tid >> 5, lane = tid & 31;
    const int wm = wid >> 1, wn = wid & 1;           // 2x2 warps, tile 64x64

    float acc[4][8][4];
#pragma unroll
    for (int i = 0; i < 4; i++)
#pragma unroll
        for (int j = 0; j < 8; j++)
#pragma unroll
            for (int l = 0; l < 4; l++) acc[i][j][l] = 0.f;

    auto load_chunk = [&](int kf) {
        const int seg = kf >> 5;
        const __nv_bfloat16* Aa = (seg == 1) ? Alo : Ahi;
        const __nv_bfloat16* Ba = (seg == 2) ? Blo : Bhi;
        const int kl = (kf & 31) * 32;
        const uint32_t base = sb + (uint32_t)(kf & 3) * STG;
#pragma unroll
        for (int i = 0; i < 4; i++) {
            int idx = tid + i * 128;
            int row = idx >> 2, q = idx & 3;
            cp16(base + row * PITCH + q * 16, Aa + (size_t)(m0 + row) * DD + kl + q * 8);
            cp16(base + ABUF + row * PITCH + q * 16, Ba + (size_t)(n0 + row) * DD + kl + q * 8);
        }
        asm volatile("cp.async.commit_group;" ::: "memory");
    };

    load_chunk(0); load_chunk(1); load_chunk(2);

    const int la = lane & 15, lb8 = (lane >> 4) * 16;
    const int rb_row = ((lane >> 4) & 1) * 8 + (lane & 7);
    const int rb_col = ((lane >> 3) & 1) * 16;
    uint32_t offa[4], offb[4];
#pragma unroll
    for (int mi = 0; mi < 4; mi++) offa[mi] = (uint32_t)((wm*64 + mi*16 + la) * PITCH + lb8);
#pragma unroll
    for (int nj = 0; nj < 4; nj++) offb[nj] = (uint32_t)((wn*64 + nj*16 + rb_row) * PITCH + rb_col);

    for (int kc = 0; kc < 96; kc++) {
        asm volatile("cp.async.wait_group 2;" ::: "memory");
        __syncthreads();

        const uint32_t As = sb + (uint32_t)(kc & 3) * STG;
        const uint32_t Bs = As + ABUF;
#pragma unroll
        for (int ks = 0; ks < 2; ks++) {
            uint32_t a[4][4], b[8][2];
#pragma unroll
            for (int mi = 0; mi < 4; mi++) ldm4(a[mi], As + offa[mi] + ks*32);
#pragma unroll
            for (int nj = 0; nj < 4; nj++) {
                uint32_t t[4];
                ldm4(t, Bs + offb[nj] + ks*32);
                b[nj*2][0] = t[0]; b[nj*2][1] = t[1];
                b[nj*2+1][0] = t[2]; b[nj*2+1][1] = t[3];
            }
            if (ks == 0) {
                if (kc + 3 < 96) load_chunk(kc + 3);
                else asm volatile("cp.async.commit_group;" ::: "memory");
            }
#pragma unroll
            for (int mi = 0; mi < 4; mi++)
#pragma unroll
                for (int ni = 0; ni < 8; ni++)
                    mma16816(acc[mi][ni], a[mi], b[ni]);
        }
    }

    const int r_lo = lane >> 2, c_lo = (lane & 3) * 2;

    if (md == 1 || md == 2) {
#pragma unroll
        for (int mi = 0; mi < 4; mi++)
#pragma unroll
            for (int ni = 0; ni < 8; ni++)
#pragma unroll
                for (int l = 0; l < 4; l++) {
                    float z = acc[mi][ni][l];
                    acc[mi][ni][l] = z * sigmoidf_(z);
                }
    }

    float inv[4][2];
#pragma unroll
    for (int mi = 0; mi < 4; mi++) { inv[mi][0] = 1.f; inv[mi][1] = 1.f; }

    if (md == 2) {
        // warp-local l2norm: this warp's 64 cols = exactly one head
#pragma unroll
        for (int mi = 0; mi < 4; mi++) {
#pragma unroll
            for (int half = 0; half < 2; half++) {
                float ss = 0.f;
#pragma unroll
                for (int ni = 0; ni < 8; ni++) {
                    float v0 = acc[mi][ni][half*2], v1 = acc[mi][ni][half*2+1];
                    ss = fmaf(v0, v0, fmaf(v1, v1, ss));
                }
                ss += __shfl_xor_sync(0xffffffffu, ss, 1);
                ss += __shfl_xor_sync(0xffffffffu, ss, 2);
                inv[mi][half] = 1.f / fmaxf(sqrtf(ss), 1e-12f);
            }
        }
    }

#pragma unroll
    for (int mi = 0; mi < 4; mi++) {
#pragma unroll
        for (int ni = 0; ni < 8; ni++) {
#pragma unroll
            for (int half = 0; half < 2; half++) {
                int row = m0 + wm*64 + mi*16 + r_lo + half*8;
                int col = wn*64 + ni*8 + c_lo;      // 0..127 within block
                float v0 = acc[mi][ni][half*2], v1 = acc[mi][ni][half*2 + 1];
                if (md == 2) { v0 *= inv[mi][half]; v1 *= inv[mi][half]; }
                if (md == 3) {
#pragma unroll
                    for (int e = 0; e < 2; e++) {
                        int cc = col + e;
                        float z = e ? v1 : v0;
                        if (cc < 16)      g_g [(size_t)row*HH + cc]        = sigmoidf_(z);
                        else if (cc < 32) g_f [(size_t)row*HH + cc - 16]   = sigmoidf_(z);
                        else if (cc < 96) g_g1[(size_t)row*HDIM + cc - 32] = z;
                    }
                } else {
                    *(float2*)(C + (size_t)row * DD + n0 + col) = make_float2(v0, v1);
                }
            }
        }
    }
}

__global__ __launch_bounds__(128, 2) void gemm_qkv() {
    const int tn = blockIdx.x, m0 = blockIdx.y * 128;
    if (tn < 8)        gemm_core(g_xhi, g_xlo, g_wqhi, g_wqlo, g_q, 1, m0, tn*128);
    else if (tn == 8)  gemm_core(g_xhi, g_xlo, g_wshi, g_wslo, g_q, 3, m0, 0);
    else if (tn < 17)  gemm_core(g_xhi, g_xlo, g_wkhi, g_wklo, g_k, 2, m0, (tn-9)*128);
    else               gemm_core(g_xhi, g_xlo, g_wvhi, g_wvlo, g_v, 1, m0, (tn-17)*128);
}
__global__ __launch_bounds__(128, 2) void gemm_out(float* __restrict__ C) {
    gemm_core(g_nhi, g_nlo, g_wohi, g_wolo, C, 0, blockIdx.y * 128, blockIdx.x * 128);
}

__global__ void dummy_kernel() { g_dummy[threadIdx.x] = 0.f; }

// ---------------- recurrence: R11 version (known 198.8us) --------------------
#define R_KS 0
#define R_QS 4096
#define R_VS 8192
#define R_FS 9216
#define R_GS 9280
#define R_PO 9344
#define RSMEM_BYTES ((9344 + 32*136) * 4)
__global__ __launch_bounds__(128) void recur_kernel() {
    extern __shared__ float rs[];
    const int blk = blockIdx.x;
    const int bh = blk >> 2, qtr = blk & 3;
    const int b = bh >> 4, h = bh & 15;
    const int tid = threadIdx.x;
    const int w = tid >> 5, lane = tid & 31;
    const int col_local = w*4 + (lane & 3);
    const int seg = lane >> 2;
    const int r0 = seg * 8;

    const size_t basev = (size_t)b*NNTOK*DD + h*HDIM;
    const size_t basef = (size_t)b*NNTOK*HH + h;

    auto stage = [&](int tile) {
        const int buf = tile & 1;
        const int t0 = tile * RT;
        const float* kg = g_k + basev + (size_t)t0 * DD;
        const float* qg = g_q + basev + (size_t)t0 * DD;
        const float* vg = g_v + basev + (size_t)t0 * DD + qtr*16;
#pragma unroll
        for (int p = 0; p < 4; p++) {
            int idx = tid + p*128;
            int r = idx >> 4, i = (idx & 15) * 4;
            cp16(s2u(rs + R_KS + buf*2048 + r*64 + i), kg + (size_t)r*DD + i);
            cp16(s2u(rs + R_QS + buf*2048 + r*64 + i), qg + (size_t)r*DD + i);
        }
        {
            int r = tid >> 2, i = (tid & 3) * 4;
            cp16(s2u(rs + R_VS + buf*512 + r*16 + i), vg + (size_t)r*DD + i);
        }
        if (tid < RT)        cp4(s2u(rs + R_FS + buf*32 + tid),      g_f + basef + (size_t)(t0+tid)*HH);
        else if (tid < 2*RT) cp4(s2u(rs + R_GS + buf*32 + (tid-RT)), g_g + basef + (size_t)(t0+tid-RT)*HH);
        asm volatile("cp.async.commit_group;" ::: "memory");
    };

    float S[8];
#pragma unroll
    for (int i = 0; i < 8; i++) S[i] = 0.f;

    stage(0);
    const int NT = NNTOK / RT;
    for (int tile = 0; tile < NT; tile++) {
        const int buf = tile & 1;
        __syncthreads();
        if (tile + 1 < NT) {
            stage(tile + 1);
            asm volatile("cp.async.wait_group 1;" ::: "memory");
        } else {
            asm volatile("cp.async.wait_group 0;" ::: "memory");
        }
        __syncthreads();

        const float* kb_ = rs + R_KS + buf*2048 + r0;
        const float* qb_ = rs + R_QS + buf*2048 + r0;
        const float* vb_ = rs + R_VS + buf*512 + col_local;
        const float* fb_ = rs + R_FS + buf*32;
        const float* gb_ = rs + R_GS + buf*32;

        float kA[8], qA[8], vA, fA, gA;
        *(float4*)(kA)   = *(const float4*)(kb_);
        *(float4*)(kA+4) = *(const float4*)(kb_+4);
        *(float4*)(qA)   = *(const float4*)(qb_);
        *(float4*)(qA+4) = *(const float4*)(qb_+4);
        vA = vb_[0]; fA = fb_[0]; gA = gb_[0];

#pragma unroll
        for (int tt = 0; tt < RT; tt++) {
            const int nx = (tt + 1 < RT) ? (tt + 1) : (RT - 1);
            float kB[8], qB[8], vB, fB, gB;
            *(float4*)(kB)   = *(const float4*)(kb_ + nx*64);
            *(float4*)(kB+4) = *(const float4*)(kb_ + nx*64 + 4);
            *(float4*)(qB)   = *(const float4*)(qb_ + nx*64);
            *(float4*)(qB+4) = *(const float4*)(qb_ + nx*64 + 4);
            vB = vb_[nx*16]; fB = fb_[nx]; gB = gb_[nx];

            const float cc = -gA * fA * fA;
            float p0 = 0.f, p1 = 0.f;
#pragma unroll
            for (int i = 0; i < 4; i++) {
                p0 = fmaf(kA[i],   S[i],   p0);
                p1 = fmaf(kA[i+4], S[i+4], p1);
            }
            float d = p0 + p1;
            d += __shfl_xor_sync(0xffffffffu, d, 4);
            d += __shfl_xor_sync(0xffffffffu, d, 8);
            d += __shfl_xor_sync(0xffffffffu, d, 16);

            const float u = fmaf(cc, d, vA);
            float o0 = 0.f, o1 = 0.f;
#pragma unroll
            for (int i = 0; i < 4; i++) {
                S[i]   = fmaf(fA, S[i],   kA[i]   * u); o0 = fmaf(qA[i],   S[i],   o0);
                S[i+4] = fmaf(fA, S[i+4], kA[i+4] * u); o1 = fmaf(qA[i+4], S[i+4], o1);
            }
            rs[R_PO + tt*136 + seg*17 + col_local] = o0 + o1;

#pragma unroll
            for (int i = 0; i < 8; i++) { kA[i] = kB[i]; qA[i] = qB[i]; }
            vA = vB; fA = fB; gA = gB;
        }
        __syncthreads();

        {
            const int colr = tid & 15, tg = tid >> 4;
#pragma unroll
            for (int rep = 0; rep < 4; rep++) {
                int t = tg + rep*8;
                float s = 0.f;
#pragma unroll
                for (int sg = 0; sg < 8; sg++) s += rs[R_PO + t*136 + sg*17 + colr];
                g_o[basev + (size_t)(tile*RT + t)*DD + qtr*16 + colr] = s;
            }
        }
    }
}

// -------- gate + LayerNorm -> bf16 hi/lo split (vectorized) ------------------
__global__ __launch_bounds__(256) void gate_ln_kernel(const float* __restrict__ Wg2,
                                                      const float* __restrict__ nw) {
    __shared__ float g1s[8 * 64];
    __shared__ float rb[8 * 1024];
    const int row0 = blockIdx.x * 8;
    const int tid = threadIdx.x;
    for (int i = tid; i < 512; i += 256) g1s[i] = g_g1[(size_t)row0 * 64 + i];
    __syncthreads();

    float a[8][4];
#pragma unroll
    for (int r = 0; r < 8; r++)
#pragma unroll
        for (int ch = 0; ch < 4; ch++) a[r][ch] = 0.f;

    for (int k4 = 0; k4 < 64; k4 += 4) {
        float4 gr[8];
#pragma unroll
        for (int r = 0; r < 8; r++) gr[r] = *(const float4*)&g1s[r*64 + k4];
#pragma unroll
        for (int ch = 0; ch < 4; ch++) {
            const int c = tid + ch * 256;
            float w0 = Wg2[(size_t)(k4+0)*DD + c];
            float w1 = Wg2[(size_t)(k4+1)*DD + c];
            float w2 = Wg2[(size_t)(k4+2)*DD + c];
            float w3 = Wg2[(size_t)(k4+3)*DD + c];
#pragma unroll
            for (int r = 0; r < 8; r++) {
                float t = fmaf(gr[r].x, w0, fmaf(gr[r].y, w1, fmaf(gr[r].z, w2, gr[r].w * w3)));
                a[r][ch] += t;
            }
        }
    }
#pragma unroll
    for (int ch = 0; ch < 4; ch++) {
        const int c = tid + ch * 256;
#pragma unroll
        for (int r = 0; r < 8; r++)
            rb[r * 1024 + c] = g_o[(size_t)(row0 + r) * DD + c] * sigmoidf_(a[r][ch]);
    }
    __syncthreads();
    const int wr = tid >> 5, ln = tid & 31;
    float s = 0.f, s2 = 0.f;
#pragma unroll 8
    for (int i = 0; i < 32; i++) {
        float v = rb[wr * 1024 + ln + 32 * i];
        s += v; s2 = fmaf(v, v, s2);
    }
#pragma unroll
    for (int o = 16; o; o >>= 1) {
        s  += __shfl_xor_sync(0xffffffffu, s,  o);
        s2 += __shfl_xor_sync(0xffffffffu, s2, o);
    }
    const float mu = s * (1.f / 1024.f);
    const float rstd = rsqrtf(s2 * (1.f / 1024.f) - mu * mu + 1e-5f);
#pragma unroll 8
    for (int i = 0; i < 32; i++) {
        int c = ln + 32 * i;
        float v = (rb[wr * 1024 + c] - mu) * rstd * nw[c];
        __nv_bfloat16 hi = __float2bfloat16(v);
        size_t idx = (size_t)(row0 + wr) * DD + c;
        g_nhi[idx] = hi;
        g_nlo[idx] = __float2bfloat16(v - __bfloat162float(hi));
    }
}

// -----------------------------------------------------------------------------
extern "C" void kernel_launch(void* const* d_in, const int* in_sizes, int n_in,
                              void* d_out, int out_size) {
    const float* x      = (const float*)d_in[0];
    const float* Wq     = (const float*)d_in[1];
    const float* Wk     = (const float*)d_in[2];
    const float* Wv     = (const float*)d_in[3];
    const float* Wgamma = (const float*)d_in[4];
    const float* Wf     = (const float*)d_in[5];
    const float* Wg1    = (const float*)d_in[6];
    const float* Wg2    = (const float*)d_in[7];
    const float* Wo     = (const float*)d_in[8];
    const float* norm_w = (const float*)d_in[9];
    float* out = (float*)d_out;

    cudaFuncSetAttribute(gemm_qkv, cudaFuncAttributeMaxDynamicSharedMemorySize, GSMEM);
    cudaFuncSetAttribute(gemm_out, cudaFuncAttributeMaxDynamicSharedMemorySize, GSMEM);
    cudaFuncSetAttribute(recur_kernel, cudaFuncAttributeMaxDynamicSharedMemorySize, RSMEM_BYTES);

    dummy_kernel<<<1, 32>>>();                                                      // 0
    prep_kernel<<<16384 + 4096 + 128, 256>>>(x, Wq, Wk, Wv, Wo, Wgamma, Wf, Wg1);  // 1
    dummy_kernel<<<1, 32>>>();                                                      // 2
    gemm_qkv<<<dim3(25, 32), 128, GSMEM>>>();                                       // 3 <- profiled
    recur_kernel<<<128, 128, RSMEM_BYTES>>>();                                      // 4
    gate_ln_kernel<<<BN/8, 256>>>(Wg2, norm_w);                                     // 5
    gemm_out<<<dim3(8, 32), 128, GSMEM>>>(out);                                     // 6
}

// round 14
// speedup vs baseline: 1.5111x; 1.2213x over previous
#include <cuda_runtime.h>
#include <cuda_fp16.h>
#include <math.h>
#include <stdint.h>

#define BB 2
#define NNTOK 2048
#define DD 1024
#define HH 16
#define HDIM 64
#define BN (BB*NNTOK)
#define RT 32
#define NCH 64   /* 2-term fp16 split: K' = 2048 = 64 chunks of 32 */

// ---------------- scratch (device globals) ----------------------------------
__device__ __half g_xhi[BN*DD], g_xlo[BN*DD];
__device__ __half g_nhi[BN*DD], g_nlo[BN*DD];
__device__ __half g_wq[DD*DD], g_wk[DD*DD], g_wv[DD*DD], g_wo[DD*DD];
__device__ __half g_ws[128*DD];
__device__ float g_q [BN*DD];
__device__ float g_k [BN*DD];
__device__ float g_v [BN*DD];
__device__ float g_o [BN*DD];
__device__ float g_f [BN*HH];
__device__ float g_g [BN*HH];
__device__ float g_g1[BN*HDIM];
__device__ float g_dummy[32];

__device__ __forceinline__ float sigmoidf_(float x) { return 1.f / (1.f + expf(-x)); }

__device__ __forceinline__ uint32_t s2u(const void* p) {
    uint32_t a;
    asm("{ .reg .u64 t; cvta.to.shared.u64 t, %1; cvt.u32.u64 %0, t; }" : "=r"(a) : "l"(p));
    return a;
}
__device__ __forceinline__ void cp16(uint32_t dst, const void* src) {
    asm volatile("cp.async.cg.shared.global [%0], [%1], 16;" :: "r"(dst), "l"(src) : "memory");
}
__device__ __forceinline__ void cp4(uint32_t dst, const void* src) {
    asm volatile("cp.async.ca.shared.global [%0], [%1], 4;" :: "r"(dst), "l"(src) : "memory");
}
__device__ __forceinline__ void ldm4(uint32_t* r, uint32_t addr) {
    asm volatile("ldmatrix.sync.aligned.m8n8.x4.shared.b16 {%0,%1,%2,%3}, [%4];"
        : "=r"(r[0]), "=r"(r[1]), "=r"(r[2]), "=r"(r[3]) : "r"(addr));
}
__device__ __forceinline__ void mma16816(float* d, const uint32_t* a, const uint32_t* b) {
    asm volatile("mma.sync.aligned.m16n8k16.row.col.f32.f16.f16.f32 "
        "{%0,%1,%2,%3}, {%4,%5,%6,%7}, {%8,%9}, {%0,%1,%2,%3};"
        : "+f"(d[0]), "+f"(d[1]), "+f"(d[2]), "+f"(d[3])
        : "r"(a[0]), "r"(a[1]), "r"(a[2]), "r"(a[3]), "r"(b[0]), "r"(b[1]));
}

// ---------------- merged prep ------------------------------------------------
__global__ __launch_bounds__(256) void prep_kernel(
    const float* __restrict__ x,
    const float* __restrict__ Wq, const float* __restrict__ Wk,
    const float* __restrict__ Wv, const float* __restrict__ Wo,
    const float* __restrict__ Wg, const float* __restrict__ Wf,
    const float* __restrict__ Wg1)
{
    __shared__ float ts[32][33];
    const int bid = blockIdx.x, tid = threadIdx.x;
    if (bid < 16384) {                    // x -> fp16 hi/lo
        int i = bid * 256 + tid;
        float v = x[i];
        __half h = __float2half_rn(v);
        g_xhi[i] = h;
        g_xlo[i] = __float2half_rn(v - __half2float(h));
    } else if (bid < 16384 + 4096) {      // weight transposes, hi only
        int t = bid - 16384;
        int z = t >> 10, rem = t & 1023;
        int bx = rem & 31, by = rem >> 5;
        const float* W; __half* hi;
        switch (z) {
            case 0:  W = Wq; hi = g_wq; break;
            case 1:  W = Wk; hi = g_wk; break;
            case 2:  W = Wv; hi = g_wv; break;
            default: W = Wo; hi = g_wo; break;
        }
        const int r = tid >> 5, c = tid & 31;
#pragma unroll
        for (int i = 0; i < 4; i++)
            ts[r + 8*i][c] = W[(size_t)(by*32 + r + 8*i) * DD + bx*32 + c];
        __syncthreads();
#pragma unroll
        for (int i = 0; i < 4; i++) {
            int n = bx*32 + r + 8*i, k = by*32 + c;
            hi[(size_t)n*DD + k] = __float2half_rn(ts[c][r + 8*i]);
        }
    } else {                              // small weights, hi only
        int n = bid - (16384 + 4096);
        for (int k = tid; k < DD; k += 256) {
            float v = (n < 16) ? Wg[(size_t)k*16 + n] : (n < 32) ? Wf[(size_t)k*16 + n - 16]
                    : (n < 96) ? Wg1[(size_t)k*64 + n - 32] : 0.f;
            g_ws[(size_t)n*DD + k] = __float2half_rn(v);
        }
    }
}

// ---------------- fp16 2-term split GEMM: 4 warps, warp tile 64x64 ------------
#define PITCH 80
#define ABUF (128*PITCH)
#define STG (2*ABUF)
#define GSMEM (4*STG)
__device__ __forceinline__ void gemm_core(
    const __half* __restrict__ Ahi, const __half* __restrict__ Alo,
    const __half* __restrict__ Bhi,
    float* __restrict__ C, int md, int m0, int n0)
{
    extern __shared__ __align__(16) char sm[];
    const uint32_t sb = s2u(sm);
    const int tid = threadIdx.x, wid = tid >> 5, lane = tid & 31;
    const int wm = wid >> 1, wn = wid & 1;           // 2x2 warps, tile 64x64

    float acc[4][8][4];
#pragma unroll
    for (int i = 0; i < 4; i++)
#pragma unroll
        for (int j = 0; j < 8; j++)
#pragma unroll
            for (int l = 0; l < 4; l++) acc[i][j][l] = 0.f;

    auto load_chunk = [&](int kf) {
        const __half* Aa = (kf >= 32) ? Alo : Ahi;
        const int kl = (kf & 31) * 32;
        const uint32_t base = sb + (uint32_t)(kf & 3) * STG;
#pragma unroll
        for (int i = 0; i < 4; i++) {
            int idx = tid + i * 128;
            int row = idx >> 2, q = idx & 3;
            cp16(base + row * PITCH + q * 16, Aa + (size_t)(m0 + row) * DD + kl + q * 8);
            cp16(base + ABUF + row * PITCH + q * 16, Bhi + (size_t)(n0 + row) * DD + kl + q * 8);
        }
        asm volatile("cp.async.commit_group;" ::: "memory");
    };

    load_chunk(0); load_chunk(1); load_chunk(2);

    const int la = lane & 15, lb8 = (lane >> 4) * 16;
    const int rb_row = ((lane >> 4) & 1) * 8 + (lane & 7);
    const int rb_col = ((lane >> 3) & 1) * 16;
    uint32_t offa[4], offb[4];
#pragma unroll
    for (int mi = 0; mi < 4; mi++) offa[mi] = (uint32_t)((wm*64 + mi*16 + la) * PITCH + lb8);
#pragma unroll
    for (int nj = 0; nj < 4; nj++) offb[nj] = (uint32_t)((wn*64 + nj*16 + rb_row) * PITCH + rb_col);

    for (int kc = 0; kc < NCH; kc++) {
        asm volatile("cp.async.wait_group 2;" ::: "memory");
        __syncthreads();

        const uint32_t As = sb + (uint32_t)(kc & 3) * STG;
        const uint32_t Bs = As + ABUF;
#pragma unroll
        for (int ks = 0; ks < 2; ks++) {
            uint32_t a[4][4], b[8][2];
#pragma unroll
            for (int mi = 0; mi < 4; mi++) ldm4(a[mi], As + offa[mi] + ks*32);
#pragma unroll
            for (int nj = 0; nj < 4; nj++) {
                uint32_t t[4];
                ldm4(t, Bs + offb[nj] + ks*32);
                b[nj*2][0] = t[0]; b[nj*2][1] = t[1];
                b[nj*2+1][0] = t[2]; b[nj*2+1][1] = t[3];
            }
            if (ks == 0) {
                if (kc + 3 < NCH) load_chunk(kc + 3);
                else asm volatile("cp.async.commit_group;" ::: "memory");
            }
#pragma unroll
            for (int mi = 0; mi < 4; mi++)
#pragma unroll
                for (int ni = 0; ni < 8; ni++)
                    mma16816(acc[mi][ni], a[mi], b[ni]);
        }
    }

    const int r_lo = lane >> 2, c_lo = (lane & 3) * 2;

    if (md == 1 || md == 2) {
#pragma unroll
        for (int mi = 0; mi < 4; mi++)
#pragma unroll
            for (int ni = 0; ni < 8; ni++)
#pragma unroll
                for (int l = 0; l < 4; l++) {
                    float z = acc[mi][ni][l];
                    acc[mi][ni][l] = z * sigmoidf_(z);
                }
    }

    float inv[4][2];
#pragma unroll
    for (int mi = 0; mi < 4; mi++) { inv[mi][0] = 1.f; inv[mi][1] = 1.f; }

    if (md == 2) {
        // warp-local l2norm: this warp's 64 cols = exactly one head
#pragma unroll
        for (int mi = 0; mi < 4; mi++) {
#pragma unroll
            for (int half = 0; half < 2; half++) {
                float ss = 0.f;
#pragma unroll
                for (int ni = 0; ni < 8; ni++) {
                    float v0 = acc[mi][ni][half*2], v1 = acc[mi][ni][half*2+1];
                    ss = fmaf(v0, v0, fmaf(v1, v1, ss));
                }
                ss += __shfl_xor_sync(0xffffffffu, ss, 1);
                ss += __shfl_xor_sync(0xffffffffu, ss, 2);
                inv[mi][half] = 1.f / fmaxf(sqrtf(ss), 1e-12f);
            }
        }
    }

#pragma unroll
    for (int mi = 0; mi < 4; mi++) {
#pragma unroll
        for (int ni = 0; ni < 8; ni++) {
#pragma unroll
            for (int half = 0; half < 2; half++) {
                int row = m0 + wm*64 + mi*16 + r_lo + half*8;
                int col = wn*64 + ni*8 + c_lo;
                float v0 = acc[mi][ni][half*2], v1 = acc[mi][ni][half*2 + 1];
                if (md == 2) { v0 *= inv[mi][half]; v1 *= inv[mi][half]; }
                if (md == 3) {
#pragma unroll
                    for (int e = 0; e < 2; e++) {
                        int cc = col + e;
                        float z = e ? v1 : v0;
                        if (cc < 16)      g_g [(size_t)row*HH + cc]        = sigmoidf_(z);
                        else if (cc < 32) g_f [(size_t)row*HH + cc - 16]   = sigmoidf_(z);
                        else if (cc < 96) g_g1[(size_t)row*HDIM + cc - 32] = z;
                    }
                } else {
                    *(float2*)(C + (size_t)row * DD + n0 + col) = make_float2(v0, v1);
                }
            }
        }
    }
}

__global__ __launch_bounds__(128, 2) void gemm_qkv() {
    const int tn = blockIdx.x, m0 = blockIdx.y * 128;
    if (tn < 8)        gemm_core(g_xhi, g_xlo, g_wq, g_q, 1, m0, tn*128);
    else if (tn == 8)  gemm_core(g_xhi, g_xlo, g_ws, g_q, 3, m0, 0);
    else if (tn < 17)  gemm_core(g_xhi, g_xlo, g_wk, g_k, 2, m0, (tn-9)*128);
    else               gemm_core(g_xhi, g_xlo, g_wv, g_v, 1, m0, (tn-17)*128);
}
__global__ __launch_bounds__(128, 2) void gemm_out(float* __restrict__ C) {
    gemm_core(g_nhi, g_nlo, g_wo, C, 0, blockIdx.y * 128, blockIdx.x * 128);
}

__global__ void dummy_kernel() { g_dummy[threadIdx.x] = 0.f; }

// ---------------- recurrence: R11 version (known 198.8us) --------------------
#define R_KS 0
#define R_QS 4096
#define R_VS 8192
#define R_FS 9216
#define R_GS 9280
#define R_PO 9344
#define RSMEM_BYTES ((9344 + 32*136) * 4)
__global__ __launch_bounds__(128) void recur_kernel() {
    extern __shared__ float rs[];
    const int blk = blockIdx.x;
    const int bh = blk >> 2, qtr = blk & 3;
    const int b = bh >> 4, h = bh & 15;
    const int tid = threadIdx.x;
    const int w = tid >> 5, lane = tid & 31;
    const int col_local = w*4 + (lane & 3);
    const int seg = lane >> 2;
    const int r0 = seg * 8;

    const size_t basev = (size_t)b*NNTOK*DD + h*HDIM;
    const size_t basef = (size_t)b*NNTOK*HH + h;

    auto stage = [&](int tile) {
        const int buf = tile & 1;
        const int t0 = tile * RT;
        const float* kg = g_k + basev + (size_t)t0 * DD;
        const float* qg = g_q + basev + (size_t)t0 * DD;
        const float* vg = g_v + basev + (size_t)t0 * DD + qtr*16;
#pragma unroll
        for (int p = 0; p < 4; p++) {
            int idx = tid + p*128;
            int r = idx >> 4, i = (idx & 15) * 4;
            cp16(s2u(rs + R_KS + buf*2048 + r*64 + i), kg + (size_t)r*DD + i);
            cp16(s2u(rs + R_QS + buf*2048 + r*64 + i), qg + (size_t)r*DD + i);
        }
        {
            int r = tid >> 2, i = (tid & 3) * 4;
            cp16(s2u(rs + R_VS + buf*512 + r*16 + i), vg + (size_t)r*DD + i);
        }
        if (tid < RT)        cp4(s2u(rs + R_FS + buf*32 + tid),      g_f + basef + (size_t)(t0+tid)*HH);
        else if (tid < 2*RT) cp4(s2u(rs + R_GS + buf*32 + (tid-RT)), g_g + basef + (size_t)(t0+tid-RT)*HH);
        asm volatile("cp.async.commit_group;" ::: "memory");
    };

    float S[8];
#pragma unroll
    for (int i = 0; i < 8; i++) S[i] = 0.f;

    stage(0);
    const int NT = NNTOK / RT;
    for (int tile = 0; tile < NT; tile++) {
        const int buf = tile & 1;
        __syncthreads();
        if (tile + 1 < NT) {
            stage(tile + 1);
            asm volatile("cp.async.wait_group 1;" ::: "memory");
        } else {
            asm volatile("cp.async.wait_group 0;" ::: "memory");
        }
        __syncthreads();

        const float* kb_ = rs + R_KS + buf*2048 + r0;
        const float* qb_ = rs + R_QS + buf*2048 + r0;
        const float* vb_ = rs + R_VS + buf*512 + col_local;
        const float* fb_ = rs + R_FS + buf*32;
        const float* gb_ = rs + R_GS + buf*32;

        float kA[8], qA[8], vA, fA, gA;
        *(float4*)(kA)   = *(const float4*)(kb_);
        *(float4*)(kA+4) = *(const float4*)(kb_+4);
        *(float4*)(qA)   = *(const float4*)(qb_);
        *(float4*)(qA+4) = *(const float4*)(qb_+4);
        vA = vb_[0]; fA = fb_[0]; gA = gb_[0];

#pragma unroll
        for (int tt = 0; tt < RT; tt++) {
            const int nx = (tt + 1 < RT) ? (tt + 1) : (RT - 1);
            float kB[8], qB[8], vB, fB, gB;
            *(float4*)(kB)   = *(const float4*)(kb_ + nx*64);
            *(float4*)(kB+4) = *(const float4*)(kb_ + nx*64 + 4);
            *(float4*)(qB)   = *(const float4*)(qb_ + nx*64);
            *(float4*)(qB+4) = *(const float4*)(qb_ + nx*64 + 4);
            vB = vb_[nx*16]; fB = fb_[nx]; gB = gb_[nx];

            const float cc = -gA * fA * fA;
            float p0 = 0.f, p1 = 0.f;
#pragma unroll
            for (int i = 0; i < 4; i++) {
                p0 = fmaf(kA[i],   S[i],   p0);
                p1 = fmaf(kA[i+4], S[i+4], p1);
            }
            float d = p0 + p1;
            d += __shfl_xor_sync(0xffffffffu, d, 4);
            d += __shfl_xor_sync(0xffffffffu, d, 8);
            d += __shfl_xor_sync(0xffffffffu, d, 16);

            const float u = fmaf(cc, d, vA);
            float o0 = 0.f, o1 = 0.f;
#pragma unroll
            for (int i = 0; i < 4; i++) {
                S[i]   = fmaf(fA, S[i],   kA[i]   * u); o0 = fmaf(qA[i],   S[i],   o0);
                S[i+4] = fmaf(fA, S[i+4], kA[i+4] * u); o1 = fmaf(qA[i+4], S[i+4], o1);
            }
            rs[R_PO + tt*136 + seg*17 + col_local] = o0 + o1;

#pragma unroll
            for (int i = 0; i < 8; i++) { kA[i] = kB[i]; qA[i] = qB[i]; }
            vA = vB; fA = fB; gA = gB;
        }
        __syncthreads();

        {
            const int colr = tid & 15, tg = tid >> 4;
#pragma unroll
            for (int rep = 0; rep < 4; rep++) {
                int t = tg + rep*8;
                float s = 0.f;
#pragma unroll
                for (int sg = 0; sg < 8; sg++) s += rs[R_PO + t*136 + sg*17 + colr];
                g_o[basev + (size_t)(tile*RT + t)*DD + qtr*16 + colr] = s;
            }
        }
    }
}

// -------- gate + LayerNorm -> fp16 hi/lo split -------------------------------
__global__ __launch_bounds__(256) void gate_ln_kernel(const float* __restrict__ Wg2,
                                                      const float* __restrict__ nw) {
    __shared__ float g1s[8 * 64];
    __shared__ float rb[8 * 1024];
    const int row0 = blockIdx.x * 8;
    const int tid = threadIdx.x;
    for (int i = tid; i < 512; i += 256) g1s[i] = g_g1[(size_t)row0 * 64 + i];
    __syncthreads();

    float a[8][4];
#pragma unroll
    for (int r = 0; r < 8; r++)
#pragma unroll
        for (int ch = 0; ch < 4; ch++) a[r][ch] = 0.f;

    for (int k4 = 0; k4 < 64; k4 += 4) {
        float4 gr[8];
#pragma unroll
        for (int r = 0; r < 8; r++) gr[r] = *(const float4*)&g1s[r*64 + k4];
#pragma unroll
        for (int ch = 0; ch < 4; ch++) {
            const int c = tid + ch * 256;
            float w0 = Wg2[(size_t)(k4+0)*DD + c];
            float w1 = Wg2[(size_t)(k4+1)*DD + c];
            float w2 = Wg2[(size_t)(k4+2)*DD + c];
            float w3 = Wg2[(size_t)(k4+3)*DD + c];
#pragma unroll
            for (int r = 0; r < 8; r++) {
                float t = fmaf(gr[r].x, w0, fmaf(gr[r].y, w1, fmaf(gr[r].z, w2, gr[r].w * w3)));
                a[r][ch] += t;
            }
        }
    }
#pragma unroll
    for (int ch = 0; ch < 4; ch++) {
        const int c = tid + ch * 256;
#pragma unroll
        for (int r = 0; r < 8; r++)
            rb[r * 1024 + c] = g_o[(size_t)(row0 + r) * DD + c] * sigmoidf_(a[r][ch]);
    }
    __syncthreads();
    const int wr = tid >> 5, ln = tid & 31;
    float s = 0.f, s2 = 0.f;
#pragma unroll 8
    for (int i = 0; i < 32; i++) {
        float v = rb[wr * 1024 + ln + 32 * i];
        s += v; s2 = fmaf(v, v, s2);
    }
#pragma unroll
    for (int o = 16; o; o >>= 1) {
        s  += __shfl_xor_sync(0xffffffffu, s,  o);
        s2 += __shfl_xor_sync(0xffffffffu, s2, o);
    }
    const float mu = s * (1.f / 1024.f);
    const float rstd = rsqrtf(s2 * (1.f / 1024.f) - mu * mu + 1e-5f);
#pragma unroll 8
    for (int i = 0; i < 32; i++) {
        int c = ln + 32 * i;
        float v = (rb[wr * 1024 + c] - mu) * rstd * nw[c];
        __half hi = __float2half_rn(v);
        size_t idx = (size_t)(row0 + wr) * DD + c;
        g_nhi[idx] = hi;
        g_nlo[idx] = __float2half_rn(v - __half2float(hi));
    }
}

// -----------------------------------------------------------------------------
extern "C" void kernel_launch(void* const* d_in, const int* in_sizes, int n_in,
                              void* d_out, int out_size) {
    const float* x      = (const float*)d_in[0];
    const float* Wq     = (const float*)d_in[1];
    const float* Wk     = (const float*)d_in[2];
    const float* Wv     = (const float*)d_in[3];
    const float* Wgamma = (const float*)d_in[4];
    const float* Wf     = (const float*)d_in[5];
    const float* Wg1    = (const float*)d_in[6];
    const float* Wg2    = (const float*)d_in[7];
    const float* Wo     = (const float*)d_in[8];
    const float* norm_w = (const float*)d_in[9];
    float* out = (float*)d_out;

    cudaFuncSetAttribute(gemm_qkv, cudaFuncAttributeMaxDynamicSharedMemorySize, GSMEM);
    cudaFuncSetAttribute(gemm_out, cudaFuncAttributeMaxDynamicSharedMemorySize, GSMEM);
    cudaFuncSetAttribute(recur_kernel, cudaFuncAttributeMaxDynamicSharedMemorySize, RSMEM_BYTES);

    dummy_kernel<<<1, 32>>>();                                                      // 0
    prep_kernel<<<16384 + 4096 + 128, 256>>>(x, Wq, Wk, Wv, Wo, Wgamma, Wf, Wg1);  // 1
    dummy_kernel<<<1, 32>>>();                                                      // 2
    gemm_qkv<<<dim3(25, 32), 128, GSMEM>>>();                                       // 3 <- profiled
    recur_kernel<<<128, 128, RSMEM_BYTES>>>();                                      // 4
    gate_ln_kernel<<<BN/8, 256>>>(Wg2, norm_w);                                     // 5
    gemm_out<<<dim3(8, 32), 128, GSMEM>>>(out);                                     // 6
}

// round 15
// speedup vs baseline: 1.5128x; 1.0011x over previous
#include <cuda_runtime.h>
#include <cuda_fp16.h>
#include <math.h>
#include <stdint.h>

#define BB 2
#define NNTOK 2048
#define DD 1024
#define HH 16
#define HDIM 64
#define BN (BB*NNTOK)
#define RT 32
#define NCH 64   /* 2-term fp16 split: K' = 2048 = 64 chunks of 32 */

// ---------------- scratch (device globals) ----------------------------------
__device__ __half g_xhi[BN*DD], g_xlo[BN*DD];
__device__ __half g_nhi[BN*DD], g_nlo[BN*DD];
__device__ __half g_wq[DD*DD], g_wk[DD*DD], g_wv[DD*DD], g_wo[DD*DD];
__device__ __half g_ws[128*DD];
__device__ float g_q [BN*DD];
__device__ float g_k [BN*DD];
__device__ float g_v [BN*DD];
__device__ float g_o [BN*DD];
__device__ float g_f [BN*HH];
__device__ float g_g [BN*HH];
__device__ float g_g1[BN*HDIM];
__device__ float g_dummy[32];

__device__ __forceinline__ float sigmoidf_(float x) { return 1.f / (1.f + expf(-x)); }

__device__ __forceinline__ uint32_t s2u(const void* p) {
    uint32_t a;
    asm("{ .reg .u64 t; cvta.to.shared.u64 t, %1; cvt.u32.u64 %0, t; }" : "=r"(a) : "l"(p));
    return a;
}
__device__ __forceinline__ void cp16(uint32_t dst, const void* src) {
    asm volatile("cp.async.cg.shared.global [%0], [%1], 16;" :: "r"(dst), "l"(src) : "memory");
}
__device__ __forceinline__ void cp4(uint32_t dst, const void* src) {
    asm volatile("cp.async.ca.shared.global [%0], [%1], 4;" :: "r"(dst), "l"(src) : "memory");
}
__device__ __forceinline__ void ldm4(uint32_t* r, uint32_t addr) {
    asm volatile("ldmatrix.sync.aligned.m8n8.x4.shared.b16 {%0,%1,%2,%3}, [%4];"
        : "=r"(r[0]), "=r"(r[1]), "=r"(r[2]), "=r"(r[3]) : "r"(addr));
}
__device__ __forceinline__ void mma16816(float* d, const uint32_t* a, const uint32_t* b) {
    asm volatile("mma.sync.aligned.m16n8k16.row.col.f32.f16.f16.f32 "
        "{%0,%1,%2,%3}, {%4,%5,%6,%7}, {%8,%9}, {%0,%1,%2,%3};"
        : "+f"(d[0]), "+f"(d[1]), "+f"(d[2]), "+f"(d[3])
        : "r"(a[0]), "r"(a[1]), "r"(a[2]), "r"(a[3]), "r"(b[0]), "r"(b[1]));
}

// ---------------- merged prep ------------------------------------------------
__global__ __launch_bounds__(256) void prep_kernel(
    const float* __restrict__ x,
    const float* __restrict__ Wq, const float* __restrict__ Wk,
    const float* __restrict__ Wv, const float* __restrict__ Wo,
    const float* __restrict__ Wg, const float* __restrict__ Wf,
    const float* __restrict__ Wg1)
{
    __shared__ float ts[32][33];
    const int bid = blockIdx.x, tid = threadIdx.x;
    if (bid < 16384) {                    // x -> fp16 hi/lo
        int i = bid * 256 + tid;
        float v = x[i];
        __half h = __float2half_rn(v);
        g_xhi[i] = h;
        g_xlo[i] = __float2half_rn(v - __half2float(h));
    } else if (bid < 16384 + 4096) {      // weight transposes, hi only
        int t = bid - 16384;
        int z = t >> 10, rem = t & 1023;
        int bx = rem & 31, by = rem >> 5;
        const float* W; __half* hi;
        switch (z) {
            case 0:  W = Wq; hi = g_wq; break;
            case 1:  W = Wk; hi = g_wk; break;
            case 2:  W = Wv; hi = g_wv; break;
            default: W = Wo; hi = g_wo; break;
        }
        const int r = tid >> 5, c = tid & 31;
#pragma unroll
        for (int i = 0; i < 4; i++)
            ts[r + 8*i][c] = W[(size_t)(by*32 + r + 8*i) * DD + bx*32 + c];
        __syncthreads();
#pragma unroll
        for (int i = 0; i < 4; i++) {
            int n = bx*32 + r + 8*i, k = by*32 + c;
            hi[(size_t)n*DD + k] = __float2half_rn(ts[c][r + 8*i]);
        }
    } else {                              // small weights, hi only
        int n = bid - (16384 + 4096);
        for (int k = tid; k < DD; k += 256) {
            float v = (n < 16) ? Wg[(size_t)k*16 + n] : (n < 32) ? Wf[(size_t)k*16 + n - 16]
                    : (n < 96) ? Wg1[(size_t)k*64 + n - 32] : 0.f;
            g_ws[(size_t)n*DD + k] = __float2half_rn(v);
        }
    }
}

// ------- fp16 2-term split GEMM: 4 warps, 64x64 warp tile, 3-stage ring ------
#define PITCH 80
#define ABUF (128*PITCH)
#define STG (2*ABUF)
#define GSMEM (3*STG)   /* 61440 -> 3 CTAs/SM */
__device__ __forceinline__ void gemm_core(
    const __half* __restrict__ Ahi, const __half* __restrict__ Alo,
    const __half* __restrict__ Bhi,
    float* __restrict__ C, int md, int m0, int n0)
{
    extern __shared__ __align__(16) char sm[];
    const uint32_t sb = s2u(sm);
    const int tid = threadIdx.x, wid = tid >> 5, lane = tid & 31;
    const int wm = wid >> 1, wn = wid & 1;           // 2x2 warps, tile 64x64

    float acc[4][8][4];
#pragma unroll
    for (int i = 0; i < 4; i++)
#pragma unroll
        for (int j = 0; j < 8; j++)
#pragma unroll
            for (int l = 0; l < 4; l++) acc[i][j][l] = 0.f;

    auto load_chunk = [&](int kf) {
        const __half* Aa = (kf >= 32) ? Alo : Ahi;
        const int kl = (kf & 31) * 32;
        const uint32_t base = sb + (uint32_t)(kf % 3) * STG;
#pragma unroll
        for (int i = 0; i < 4; i++) {
            int idx = tid + i * 128;
            int row = idx >> 2, q = idx & 3;
            cp16(base + row * PITCH + q * 16, Aa + (size_t)(m0 + row) * DD + kl + q * 8);
            cp16(base + ABUF + row * PITCH + q * 16, Bhi + (size_t)(n0 + row) * DD + kl + q * 8);
        }
        asm volatile("cp.async.commit_group;" ::: "memory");
    };

    load_chunk(0); load_chunk(1);

    const int la = lane & 15, lb8 = (lane >> 4) * 16;
    const int rb_row = ((lane >> 4) & 1) * 8 + (lane & 7);
    const int rb_col = ((lane >> 3) & 1) * 16;
    uint32_t offa[4], offb[4];
#pragma unroll
    for (int mi = 0; mi < 4; mi++) offa[mi] = (uint32_t)((wm*64 + mi*16 + la) * PITCH + lb8);
#pragma unroll
    for (int nj = 0; nj < 4; nj++) offb[nj] = (uint32_t)((wn*64 + nj*16 + rb_row) * PITCH + rb_col);

    for (int kc = 0; kc < NCH; kc++) {
        if (kc + 1 < NCH) asm volatile("cp.async.wait_group 1;" ::: "memory");
        else              asm volatile("cp.async.wait_group 0;" ::: "memory");
        __syncthreads();

        const uint32_t As = sb + (uint32_t)(kc % 3) * STG;
        const uint32_t Bs = As + ABUF;
#pragma unroll
        for (int ks = 0; ks < 2; ks++) {
            uint32_t a[4][4], b[8][2];
#pragma unroll
            for (int mi = 0; mi < 4; mi++) ldm4(a[mi], As + offa[mi] + ks*32);
#pragma unroll
            for (int nj = 0; nj < 4; nj++) {
                uint32_t t[4];
                ldm4(t, Bs + offb[nj] + ks*32);
                b[nj*2][0] = t[0]; b[nj*2][1] = t[1];
                b[nj*2+1][0] = t[2]; b[nj*2+1][1] = t[3];
            }
            if (ks == 0 && kc + 2 < NCH) load_chunk(kc + 2);
#pragma unroll
            for (int mi = 0; mi < 4; mi++)
#pragma unroll
                for (int ni = 0; ni < 8; ni++)
                    mma16816(acc[mi][ni], a[mi], b[ni]);
        }
    }

    const int r_lo = lane >> 2, c_lo = (lane & 3) * 2;

    if (md == 1 || md == 2) {
#pragma unroll
        for (int mi = 0; mi < 4; mi++)
#pragma unroll
            for (int ni = 0; ni < 8; ni++)
#pragma unroll
                for (int l = 0; l < 4; l++) {
                    float z = acc[mi][ni][l];
                    acc[mi][ni][l] = z * sigmoidf_(z);
                }
    }

    float inv[4][2];
#pragma unroll
    for (int mi = 0; mi < 4; mi++) { inv[mi][0] = 1.f; inv[mi][1] = 1.f; }

    if (md == 2) {
        // warp-local l2norm: this warp's 64 cols = exactly one head
#pragma unroll
        for (int mi = 0; mi < 4; mi++) {
#pragma unroll
            for (int half = 0; half < 2; half++) {
                float ss = 0.f;
#pragma unroll
                for (int ni = 0; ni < 8; ni++) {
                    float v0 = acc[mi][ni][half*2], v1 = acc[mi][ni][half*2+1];
                    ss = fmaf(v0, v0, fmaf(v1, v1, ss));
                }
                ss += __shfl_xor_sync(0xffffffffu, ss, 1);
                ss += __shfl_xor_sync(0xffffffffu, ss, 2);
                inv[mi][half] = 1.f / fmaxf(sqrtf(ss), 1e-12f);
            }
        }
    }

#pragma unroll
    for (int mi = 0; mi < 4; mi++) {
#pragma unroll
        for (int ni = 0; ni < 8; ni++) {
#pragma unroll
            for (int half = 0; half < 2; half++) {
                int row = m0 + wm*64 + mi*16 + r_lo + half*8;
                int col = wn*64 + ni*8 + c_lo;
                float v0 = acc[mi][ni][half*2], v1 = acc[mi][ni][half*2 + 1];
                if (md == 2) { v0 *= inv[mi][half]; v1 *= inv[mi][half]; }
                if (md == 3) {
#pragma unroll
                    for (int e = 0; e < 2; e++) {
                        int cc = col + e;
                        float z = e ? v1 : v0;
                        if (cc < 16)      g_g [(size_t)row*HH + cc]        = sigmoidf_(z);
                        else if (cc < 32) g_f [(size_t)row*HH + cc - 16]   = sigmoidf_(z);
                        else if (cc < 96) g_g1[(size_t)row*HDIM + cc - 32] = z;
                    }
                } else {
                    *(float2*)(C + (size_t)row * DD + n0 + col) = make_float2(v0, v1);
                }
            }
        }
    }
}

__global__ __launch_bounds__(128, 3) void gemm_qkv() {
    const int tn = blockIdx.x, m0 = blockIdx.y * 128;
    if (tn < 8)        gemm_core(g_xhi, g_xlo, g_wq, g_q, 1, m0, tn*128);
    else if (tn == 8)  gemm_core(g_xhi, g_xlo, g_ws, g_q, 3, m0, 0);
    else if (tn < 17)  gemm_core(g_xhi, g_xlo, g_wk, g_k, 2, m0, (tn-9)*128);
    else               gemm_core(g_xhi, g_xlo, g_wv, g_v, 1, m0, (tn-17)*128);
}
__global__ __launch_bounds__(128, 3) void gemm_out(float* __restrict__ C) {
    gemm_core(g_nhi, g_nlo, g_wo, C, 0, blockIdx.y * 128, blockIdx.x * 128);
}

__global__ void dummy_kernel() { g_dummy[threadIdx.x] = 0.f; }

// ---------------- recurrence: R11 version (known 198.8us) --------------------
#define R_KS 0
#define R_QS 4096
#define R_VS 8192
#define R_FS 9216
#define R_GS 9280
#define R_PO 9344
#define RSMEM_BYTES ((9344 + 32*136) * 4)
__global__ __launch_bounds__(128) void recur_kernel() {
    extern __shared__ float rs[];
    const int blk = blockIdx.x;
    const int bh = blk >> 2, qtr = blk & 3;
    const int b = bh >> 4, h = bh & 15;
    const int tid = threadIdx.x;
    const int w = tid >> 5, lane = tid & 31;
    const int col_local = w*4 + (lane & 3);
    const int seg = lane >> 2;
    const int r0 = seg * 8;

    const size_t basev = (size_t)b*NNTOK*DD + h*HDIM;
    const size_t basef = (size_t)b*NNTOK*HH + h;

    auto stage = [&](int tile) {
        const int buf = tile & 1;
        const int t0 = tile * RT;
        const float* kg = g_k + basev + (size_t)t0 * DD;
        const float* qg = g_q + basev + (size_t)t0 * DD;
        const float* vg = g_v + basev + (size_t)t0 * DD + qtr*16;
#pragma unroll
        for (int p = 0; p < 4; p++) {
            int idx = tid + p*128;
            int r = idx >> 4, i = (idx & 15) * 4;
            cp16(s2u(rs + R_KS + buf*2048 + r*64 + i), kg + (size_t)r*DD + i);
            cp16(s2u(rs + R_QS + buf*2048 + r*64 + i), qg + (size_t)r*DD + i);
        }
        {
            int r = tid >> 2, i = (tid & 3) * 4;
            cp16(s2u(rs + R_VS + buf*512 + r*16 + i), vg + (size_t)r*DD + i);
        }
        if (tid < RT)        cp4(s2u(rs + R_FS + buf*32 + tid),      g_f + basef + (size_t)(t0+tid)*HH);
        else if (tid < 2*RT) cp4(s2u(rs + R_GS + buf*32 + (tid-RT)), g_g + basef + (size_t)(t0+tid-RT)*HH);
        asm volatile("cp.async.commit_group;" ::: "memory");
    };

    float S[8];
#pragma unroll
    for (int i = 0; i < 8; i++) S[i] = 0.f;

    stage(0);
    const int NT = NNTOK / RT;
    for (int tile = 0; tile < NT; tile++) {
        const int buf = tile & 1;
        __syncthreads();
        if (tile + 1 < NT) {
            stage(tile + 1);
            asm volatile("cp.async.wait_group 1;" ::: "memory");
        } else {
            asm volatile("cp.async.wait_group 0;" ::: "memory");
        }
        __syncthreads();

        const float* kb_ = rs + R_KS + buf*2048 + r0;
        const float* qb_ = rs + R_QS + buf*2048 + r0;
        const float* vb_ = rs + R_VS + buf*512 + col_local;
        const float* fb_ = rs + R_FS + buf*32;
        const float* gb_ = rs + R_GS + buf*32;

        float kA[8], qA[8], vA, fA, gA;
        *(float4*)(kA)   = *(const float4*)(kb_);
        *(float4*)(kA+4) = *(const float4*)(kb_+4);
        *(float4*)(qA)   = *(const float4*)(qb_);
        *(float4*)(qA+4) = *(const float4*)(qb_+4);
        vA = vb_[0]; fA = fb_[0]; gA = gb_[0];

#pragma unroll
        for (int tt = 0; tt < RT; tt++) {
            const int nx = (tt + 1 < RT) ? (tt + 1) : (RT - 1);
            float kB[8], qB[8], vB, fB, gB;
            *(float4*)(kB)   = *(const float4*)(kb_ + nx*64);
            *(float4*)(kB+4) = *(const float4*)(kb_ + nx*64 + 4);
            *(float4*)(qB)   = *(const float4*)(qb_ + nx*64);
            *(float4*)(qB+4) = *(const float4*)(qb_ + nx*64 + 4);
            vB = vb_[nx*16]; fB = fb_[nx]; gB = gb_[nx];

            const float cc = -gA * fA * fA;
            float p0 = 0.f, p1 = 0.f;
#pragma unroll
            for (int i = 0; i < 4; i++) {
                p0 = fmaf(kA[i],   S[i],   p0);
                p1 = fmaf(kA[i+4], S[i+4], p1);
            }
            float d = p0 + p1;
            d += __shfl_xor_sync(0xffffffffu, d, 4);
            d += __shfl_xor_sync(0xffffffffu, d, 8);
            d += __shfl_xor_sync(0xffffffffu, d, 16);

            const float u = fmaf(cc, d, vA);
            float o0 = 0.f, o1 = 0.f;
#pragma unroll
            for (int i = 0; i < 4; i++) {
                S[i]   = fmaf(fA, S[i],   kA[i]   * u); o0 = fmaf(qA[i],   S[i],   o0);
                S[i+4] = fmaf(fA, S[i+4], kA[i+4] * u); o1 = fmaf(qA[i+4], S[i+4], o1);
            }
            rs[R_PO + tt*136 + seg*17 + col_local] = o0 + o1;

#pragma unroll
            for (int i = 0; i < 8; i++) { kA[i] = kB[i]; qA[i] = qB[i]; }
            vA = vB; fA = fB; gA = gB;
        }
        __syncthreads();

        {
            const int colr = tid & 15, tg = tid >> 4;
#pragma unroll
            for (int rep = 0; rep < 4; rep++) {
                int t = tg + rep*8;
                float s = 0.f;
#pragma unroll
                for (int sg = 0; sg < 8; sg++) s += rs[R_PO + t*136 + sg*17 + colr];
                g_o[basev + (size_t)(tile*RT + t)*DD + qtr*16 + colr] = s;
            }
        }
    }
}

// -------- gate + LayerNorm -> fp16 hi/lo split -------------------------------
__global__ __launch_bounds__(256) void gate_ln_kernel(const float* __restrict__ Wg2,
                                                      const float* __restrict__ nw) {
    __shared__ float g1s[8 * 64];
    __shared__ float rb[8 * 1024];
    const int row0 = blockIdx.x * 8;
    const int tid = threadIdx.x;
    for (int i = tid; i < 512; i += 256) g1s[i] = g_g1[(size_t)row0 * 64 + i];
    __syncthreads();

    float a[8][4];
#pragma unroll
    for (int r = 0; r < 8; r++)
#pragma unroll
        for (int ch = 0; ch < 4; ch++) a[r][ch] = 0.f;

    for (int k4 = 0; k4 < 64; k4 += 4) {
        float4 gr[8];
#pragma unroll
        for (int r = 0; r < 8; r++) gr[r] = *(const float4*)&g1s[r*64 + k4];
#pragma unroll
        for (int ch = 0; ch < 4; ch++) {
            const int c = tid + ch * 256;
            float w0 = Wg2[(size_t)(k4+0)*DD + c];
            float w1 = Wg2[(size_t)(k4+1)*DD + c];
            float w2 = Wg2[(size_t)(k4+2)*DD + c];
            float w3 = Wg2[(size_t)(k4+3)*DD + c];
#pragma unroll
            for (int r = 0; r < 8; r++) {
                float t = fmaf(gr[r].x, w0, fmaf(gr[r].y, w1, fmaf(gr[r].z, w2, gr[r].w * w3)));
                a[r][ch] += t;
            }
        }
    }
#pragma unroll
    for (int ch = 0; ch < 4; ch++) {
        const int c = tid + ch * 256;
#pragma unroll
        for (int r = 0; r < 8; r++)
            rb[r * 1024 + c] = g_o[(size_t)(row0 + r) * DD + c] * sigmoidf_(a[r][ch]);
    }
    __syncthreads();
    const int wr = tid >> 5, ln = tid & 31;
    float s = 0.f, s2 = 0.f;
#pragma unroll 8
    for (int i = 0; i < 32; i++) {
        float v = rb[wr * 1024 + ln + 32 * i];
        s += v; s2 = fmaf(v, v, s2);
    }
#pragma unroll
    for (int o = 16; o; o >>= 1) {
        s  += __shfl_xor_sync(0xffffffffu, s,  o);
        s2 += __shfl_xor_sync(0xffffffffu, s2, o);
    }
    const float mu = s * (1.f / 1024.f);
    const float rstd = rsqrtf(s2 * (1.f / 1024.f) - mu * mu + 1e-5f);
#pragma unroll 8
    for (int i = 0; i < 32; i++) {
        int c = ln + 32 * i;
        float v = (rb[wr * 1024 + c] - mu) * rstd * nw[c];
        __half hi = __float2half_rn(v);
        size_t idx = (size_t)(row0 + wr) * DD + c;
        g_nhi[idx] = hi;
        g_nlo[idx] = __float2half_rn(v - __half2float(hi));
    }
}

// -----------------------------------------------------------------------------
extern "C" void kernel_launch(void* const* d_in, const int* in_sizes, int n_in,
                              void* d_out, int out_size) {
    const float* x      = (const float*)d_in[0];
    const float* Wq     = (const float*)d_in[1];
    const float* Wk     = (const float*)d_in[2];
    const float* Wv     = (const float*)d_in[3];
    const float* Wgamma = (const float*)d_in[4];
    const float* Wf     = (const float*)d_in[5];
    const float* Wg1    = (const float*)d_in[6];
    const float* Wg2    = (const float*)d_in[7];
    const float* Wo     = (const float*)d_in[8];
    const float* norm_w = (const float*)d_in[9];
    float* out = (float*)d_out;

    cudaFuncSetAttribute(gemm_qkv, cudaFuncAttributeMaxDynamicSharedMemorySize, GSMEM);
    cudaFuncSetAttribute(gemm_out, cudaFuncAttributeMaxDynamicSharedMemorySize, GSMEM);
    cudaFuncSetAttribute(recur_kernel, cudaFuncAttributeMaxDynamicSharedMemorySize, RSMEM_BYTES);

    dummy_kernel<<<1, 32>>>();                                                      // 0
    prep_kernel<<<16384 + 4096 + 128, 256>>>(x, Wq, Wk, Wv, Wo, Wgamma, Wf, Wg1);  // 1
    dummy_kernel<<<1, 32>>>();                                                      // 2
    gemm_qkv<<<dim3(25, 32), 128, GSMEM>>>();                                       // 3 <- profiled
    recur_kernel<<<128, 128, RSMEM_BYTES>>>();                                      // 4
    gate_ln_kernel<<<BN/8, 256>>>(Wg2, norm_w);                                     // 5
    gemm_out<<<dim3(8, 32), 128, GSMEM>>>(out);                                     // 6
}

// round 16
// speedup vs baseline: 1.5676x; 1.0362x over previous
#include <cuda_runtime.h>
#include <cuda_fp16.h>
#include <math.h>
#include <stdint.h>

#define BB 2
#define NNTOK 2048
#define DD 1024
#define HH 16
#define HDIM 64
#define BN (BB*NNTOK)
#define RT 32
#define NCH 64   /* 2-term fp16 split: K' = 2048 = 64 chunks of 32 */

// ---------------- scratch (device globals) ----------------------------------
__device__ __half g_xhi[BN*DD], g_xlo[BN*DD];
__device__ __half g_nhi[BN*DD], g_nlo[BN*DD];
__device__ __half g_wq[DD*DD], g_wk[DD*DD], g_wv[DD*DD], g_wo[DD*DD];
__device__ __half g_ws[128*DD];
__device__ float g_q [BN*DD];
__device__ float g_k [BN*DD];
__device__ float g_v [BN*DD];
__device__ float g_o [BN*DD];
__device__ float g_f [BN*HH];
__device__ float g_g [BN*HH];
__device__ float g_g1[BN*HDIM];
__device__ float g_dummy[32];

__device__ __forceinline__ float sigmoidf_(float x) { return 1.f / (1.f + expf(-x)); }

__device__ __forceinline__ uint32_t s2u(const void* p) {
    uint32_t a;
    asm("{ .reg .u64 t; cvta.to.shared.u64 t, %1; cvt.u32.u64 %0, t; }" : "=r"(a) : "l"(p));
    return a;
}
__device__ __forceinline__ void cp16(uint32_t dst, const void* src) {
    asm volatile("cp.async.cg.shared.global [%0], [%1], 16;" :: "r"(dst), "l"(src) : "memory");
}
__device__ __forceinline__ void cp4(uint32_t dst, const void* src) {
    asm volatile("cp.async.ca.shared.global [%0], [%1], 4;" :: "r"(dst), "l"(src) : "memory");
}
__device__ __forceinline__ void ldm4(uint32_t* r, uint32_t addr) {
    asm volatile("ldmatrix.sync.aligned.m8n8.x4.shared.b16 {%0,%1,%2,%3}, [%4];"
        : "=r"(r[0]), "=r"(r[1]), "=r"(r[2]), "=r"(r[3]) : "r"(addr));
}
__device__ __forceinline__ void mma16816(float* d, const uint32_t* a, const uint32_t* b) {
    asm volatile("mma.sync.aligned.m16n8k16.row.col.f32.f16.f16.f32 "
        "{%0,%1,%2,%3}, {%4,%5,%6,%7}, {%8,%9}, {%0,%1,%2,%3};"
        : "+f"(d[0]), "+f"(d[1]), "+f"(d[2]), "+f"(d[3])
        : "r"(a[0]), "r"(a[1]), "r"(a[2]), "r"(a[3]), "r"(b[0]), "r"(b[1]));
}

// ---------------- merged prep (vectorized x conversion) ----------------------
__global__ __launch_bounds__(256) void prep_kernel(
    const float* __restrict__ x,
    const float* __restrict__ Wq, const float* __restrict__ Wk,
    const float* __restrict__ Wv, const float* __restrict__ Wo,
    const float* __restrict__ Wg, const float* __restrict__ Wf,
    const float* __restrict__ Wg1)
{
    __shared__ float ts[32][33];
    const int bid = blockIdx.x, tid = threadIdx.x;
    if (bid < 4096) {                     // x -> fp16 hi/lo, 4 elems/thread
        int idx = bid * 256 + tid;        // float4 index
        float4 v4 = ((const float4*)x)[idx];
        __half h0 = __float2half_rn(v4.x), h1 = __float2half_rn(v4.y);
        __half h2 = __float2half_rn(v4.z), h3 = __float2half_rn(v4.w);
        ((__half2*)g_xhi)[idx*2  ] = __halves2half2(h0, h1);
        ((__half2*)g_xhi)[idx*2+1] = __halves2half2(h2, h3);
        ((__half2*)g_xlo)[idx*2  ] = __halves2half2(
            __float2half_rn(v4.x - __half2float(h0)), __float2half_rn(v4.y - __half2float(h1)));
        ((__half2*)g_xlo)[idx*2+1] = __halves2half2(
            __float2half_rn(v4.z - __half2float(h2)), __float2half_rn(v4.w - __half2float(h3)));
    } else if (bid < 4096 + 4096) {       // weight transposes, hi only
        int t = bid - 4096;
        int z = t >> 10, rem = t & 1023;
        int bx = rem & 31, by = rem >> 5;
        const float* W; __half* hi;
        switch (z) {
            case 0:  W = Wq; hi = g_wq; break;
            case 1:  W = Wk; hi = g_wk; break;
            case 2:  W = Wv; hi = g_wv; break;
            default: W = Wo; hi = g_wo; break;
        }
        const int r = tid >> 5, c = tid & 31;
#pragma unroll
        for (int i = 0; i < 4; i++)
            ts[r + 8*i][c] = W[(size_t)(by*32 + r + 8*i) * DD + bx*32 + c];
        __syncthreads();
#pragma unroll
        for (int i = 0; i < 4; i++) {
            int n = bx*32 + r + 8*i, k = by*32 + c;
            hi[(size_t)n*DD + k] = __float2half_rn(ts[c][r + 8*i]);
        }
    } else {                              // small weights, hi only
        int n = bid - (4096 + 4096);
        for (int k = tid; k < DD; k += 256) {
            float v = (n < 16) ? Wg[(size_t)k*16 + n] : (n < 32) ? Wf[(size_t)k*16 + n - 16]
                    : (n < 96) ? Wg1[(size_t)k*64 + n - 32] : 0.f;
            g_ws[(size_t)n*DD + k] = __float2half_rn(v);
        }
    }
}

// ------- fp16 2-term split GEMM: 4 warps, 64x64 warp tile, 4-stage ring ------
#define PITCH 80
#define ABUF (128*PITCH)
#define STG (2*ABUF)
#define GSMEM (4*STG)
__device__ __forceinline__ void gemm_core(
    const __half* __restrict__ Ahi, const __half* __restrict__ Alo,
    const __half* __restrict__ Bhi,
    float* __restrict__ C, int md, int m0, int n0)
{
    extern __shared__ __align__(16) char sm[];
    const uint32_t sb = s2u(sm);
    const int tid = threadIdx.x, wid = tid >> 5, lane = tid & 31;
    const int wm = wid >> 1, wn = wid & 1;

    float acc[4][8][4];
#pragma unroll
    for (int i = 0; i < 4; i++)
#pragma unroll
        for (int j = 0; j < 8; j++)
#pragma unroll
            for (int l = 0; l < 4; l++) acc[i][j][l] = 0.f;

    auto load_chunk = [&](int kf) {
        const __half* Aa = (kf >= 32) ? Alo : Ahi;
        const int kl = (kf & 31) * 32;
        const uint32_t base = sb + (uint32_t)(kf & 3) * STG;
#pragma unroll
        for (int i = 0; i < 4; i++) {
            int idx = tid + i * 128;
            int row = idx >> 2, q = idx & 3;
            cp16(base + row * PITCH + q * 16, Aa + (size_t)(m0 + row) * DD + kl + q * 8);
            cp16(base + ABUF + row * PITCH + q * 16, Bhi + (size_t)(n0 + row) * DD + kl + q * 8);
        }
        asm volatile("cp.async.commit_group;" ::: "memory");
    };

    load_chunk(0); load_chunk(1); load_chunk(2);

    const int la = lane & 15, lb8 = (lane >> 4) * 16;
    const int rb_row = ((lane >> 4) & 1) * 8 + (lane & 7);
    const int rb_col = ((lane >> 3) & 1) * 16;
    uint32_t offa[4], offb[4];
#pragma unroll
    for (int mi = 0; mi < 4; mi++) offa[mi] = (uint32_t)((wm*64 + mi*16 + la) * PITCH + lb8);
#pragma unroll
    for (int nj = 0; nj < 4; nj++) offb[nj] = (uint32_t)((wn*64 + nj*16 + rb_row) * PITCH + rb_col);

    for (int kc = 0; kc < NCH; kc++) {
        asm volatile("cp.async.wait_group 2;" ::: "memory");
        __syncthreads();

        const uint32_t As = sb + (uint32_t)(kc & 3) * STG;
        const uint32_t Bs = As + ABUF;
#pragma unroll
        for (int ks = 0; ks < 2; ks++) {
            uint32_t a[4][4], b[8][2];
#pragma unroll
            for (int mi = 0; mi < 4; mi++) ldm4(a[mi], As + offa[mi] + ks*32);
#pragma unroll
            for (int nj = 0; nj < 4; nj++) {
                uint32_t t[4];
                ldm4(t, Bs + offb[nj] + ks*32);
                b[nj*2][0] = t[0]; b[nj*2][1] = t[1];
                b[nj*2+1][0] = t[2]; b[nj*2+1][1] = t[3];
            }
            if (ks == 0) {
                if (kc + 3 < NCH) load_chunk(kc + 3);
                else asm volatile("cp.async.commit_group;" ::: "memory");
            }
#pragma unroll
            for (int mi = 0; mi < 4; mi++)
#pragma unroll
                for (int ni = 0; ni < 8; ni++)
                    mma16816(acc[mi][ni], a[mi], b[ni]);
        }
    }

    const int r_lo = lane >> 2, c_lo = (lane & 3) * 2;

    if (md == 1 || md == 2) {
#pragma unroll
        for (int mi = 0; mi < 4; mi++)
#pragma unroll
            for (int ni = 0; ni < 8; ni++)
#pragma unroll
                for (int l = 0; l < 4; l++) {
                    float z = acc[mi][ni][l];
                    acc[mi][ni][l] = z * sigmoidf_(z);
                }
    }

    float inv[4][2];
#pragma unroll
    for (int mi = 0; mi < 4; mi++) { inv[mi][0] = 1.f; inv[mi][1] = 1.f; }

    if (md == 2) {
#pragma unroll
        for (int mi = 0; mi < 4; mi++) {
#pragma unroll
            for (int half = 0; half < 2; half++) {
                float ss = 0.f;
#pragma unroll
                for (int ni = 0; ni < 8; ni++) {
                    float v0 = acc[mi][ni][half*2], v1 = acc[mi][ni][half*2+1];
                    ss = fmaf(v0, v0, fmaf(v1, v1, ss));
                }
                ss += __shfl_xor_sync(0xffffffffu, ss, 1);
                ss += __shfl_xor_sync(0xffffffffu, ss, 2);
                inv[mi][half] = 1.f / fmaxf(sqrtf(ss), 1e-12f);
            }
        }
    }

#pragma unroll
    for (int mi = 0; mi < 4; mi++) {
#pragma unroll
        for (int ni = 0; ni < 8; ni++) {
#pragma unroll
            for (int half = 0; half < 2; half++) {
                int row = m0 + wm*64 + mi*16 + r_lo + half*8;
                int col = wn*64 + ni*8 + c_lo;
                float v0 = acc[mi][ni][half*2], v1 = acc[mi][ni][half*2 + 1];
                if (md == 2) { v0 *= inv[mi][half]; v1 *= inv[mi][half]; }
                if (md == 3) {
#pragma unroll
                    for (int e = 0; e < 2; e++) {
                        int cc = col + e;
                        float z = e ? v1 : v0;
                        if (cc < 16)      g_g [(size_t)row*HH + cc]        = sigmoidf_(z);
                        else if (cc < 32) g_f [(size_t)row*HH + cc - 16]   = sigmoidf_(z);
                        else if (cc < 96) g_g1[(size_t)row*HDIM + cc - 32] = z;
                    }
                } else {
                    *(float2*)(C + (size_t)row * DD + n0 + col) = make_float2(v0, v1);
                }
            }
        }
    }
}

__global__ __launch_bounds__(128, 2) void gemm_qkv() {
    const int tn = blockIdx.x, m0 = blockIdx.y * 128;
    if (tn < 8)        gemm_core(g_xhi, g_xlo, g_wq, g_q, 1, m0, tn*128);
    else if (tn == 8)  gemm_core(g_xhi, g_xlo, g_ws, g_q, 3, m0, 0);
    else if (tn < 17)  gemm_core(g_xhi, g_xlo, g_wk, g_k, 2, m0, (tn-9)*128);
    else               gemm_core(g_xhi, g_xlo, g_wv, g_v, 1, m0, (tn-17)*128);
}
__global__ __launch_bounds__(128, 2) void gemm_out(float* __restrict__ C) {
    gemm_core(g_nhi, g_nlo, g_wo, C, 0, blockIdx.y * 128, blockIdx.x * 128);
}

__global__ void dummy_kernel() { g_dummy[threadIdx.x] = 0.f; }

// ---------------- recurrence: R11 + f*S precompute off critical path ---------
#define R_KS 0
#define R_QS 4096
#define R_VS 8192
#define R_FS 9216
#define R_GS 9280
#define R_PO 9344
#define RSMEM_BYTES ((9344 + 32*136) * 4)
__global__ __launch_bounds__(128) void recur_kernel() {
    extern __shared__ float rs[];
    const int blk = blockIdx.x;
    const int bh = blk >> 2, qtr = blk & 3;
    const int b = bh >> 4, h = bh & 15;
    const int tid = threadIdx.x;
    const int w = tid >> 5, lane = tid & 31;
    const int col_local = w*4 + (lane & 3);
    const int seg = lane >> 2;
    const int r0 = seg * 8;

    const size_t basev = (size_t)b*NNTOK*DD + h*HDIM;
    const size_t basef = (size_t)b*NNTOK*HH + h;

    auto stage = [&](int tile) {
        const int buf = tile & 1;
        const int t0 = tile * RT;
        const float* kg = g_k + basev + (size_t)t0 * DD;
        const float* qg = g_q + basev + (size_t)t0 * DD;
        const float* vg = g_v + basev + (size_t)t0 * DD + qtr*16;
#pragma unroll
        for (int p = 0; p < 4; p++) {
            int idx = tid + p*128;
            int r = idx >> 4, i = (idx & 15) * 4;
            cp16(s2u(rs + R_KS + buf*2048 + r*64 + i), kg + (size_t)r*DD + i);
            cp16(s2u(rs + R_QS + buf*2048 + r*64 + i), qg + (size_t)r*DD + i);
        }
        {
            int r = tid >> 2, i = (tid & 3) * 4;
            cp16(s2u(rs + R_VS + buf*512 + r*16 + i), vg + (size_t)r*DD + i);
        }
        if (tid < RT)        cp4(s2u(rs + R_FS + buf*32 + tid),      g_f + basef + (size_t)(t0+tid)*HH);
        else if (tid < 2*RT) cp4(s2u(rs + R_GS + buf*32 + (tid-RT)), g_g + basef + (size_t)(t0+tid-RT)*HH);
        asm volatile("cp.async.commit_group;" ::: "memory");
    };

    float S[8];
#pragma unroll
    for (int i = 0; i < 8; i++) S[i] = 0.f;

    stage(0);
    const int NT = NNTOK / RT;
    for (int tile = 0; tile < NT; tile++) {
        const int buf = tile & 1;
        __syncthreads();
        if (tile + 1 < NT) {
            stage(tile + 1);
            asm volatile("cp.async.wait_group 1;" ::: "memory");
        } else {
            asm volatile("cp.async.wait_group 0;" ::: "memory");
        }
        __syncthreads();

        const float* kb_ = rs + R_KS + buf*2048 + r0;
        const float* qb_ = rs + R_QS + buf*2048 + r0;
        const float* vb_ = rs + R_VS + buf*512 + col_local;
        const float* fb_ = rs + R_FS + buf*32;
        const float* gb_ = rs + R_GS + buf*32;

        float kA[8], qA[8], vA, fA, gA;
        *(float4*)(kA)   = *(const float4*)(kb_);
        *(float4*)(kA+4) = *(const float4*)(kb_+4);
        *(float4*)(qA)   = *(const float4*)(qb_);
        *(float4*)(qA+4) = *(const float4*)(qb_+4);
        vA = vb_[0]; fA = fb_[0]; gA = gb_[0];

#pragma unroll
        for (int tt = 0; tt < RT; tt++) {
            const int nx = (tt + 1 < RT) ? (tt + 1) : (RT - 1);
            float kB[8], qB[8], vB, fB, gB;
            *(float4*)(kB)   = *(const float4*)(kb_ + nx*64);
            *(float4*)(kB+4) = *(const float4*)(kb_ + nx*64 + 4);
            *(float4*)(qB)   = *(const float4*)(qb_ + nx*64);
            *(float4*)(qB+4) = *(const float4*)(qb_ + nx*64 + 4);
            vB = vb_[nx*16]; fB = fb_[nx]; gB = gb_[nx];

            const float cc = -gA * fA * fA;
            float p0 = 0.f, p1 = 0.f;
#pragma unroll
            for (int i = 0; i < 4; i++) {
                p0 = fmaf(kA[i],   S[i],   p0);
                p1 = fmaf(kA[i+4], S[i+4], p1);
            }
            // f*S precompute: independent of d, fills shfl-stall slots
            float tp[8];
#pragma unroll
            for (int i = 0; i < 8; i++) tp[i] = fA * S[i];

            float d = p0 + p1;
            d += __shfl_xor_sync(0xffffffffu, d, 4);
            d += __shfl_xor_sync(0xffffffffu, d, 8);
            d += __shfl_xor_sync(0xffffffffu, d, 16);

            const float u = fmaf(cc, d, vA);
            float o0 = 0.f, o1 = 0.f;
#pragma unroll
            for (int i = 0; i < 4; i++) {
                S[i]   = fmaf(kA[i],   u, tp[i]);   o0 = fmaf(qA[i],   S[i],   o0);
                S[i+4] = fmaf(kA[i+4], u, tp[i+4]); o1 = fmaf(qA[i+4], S[i+4], o1);
            }
            rs[R_PO + tt*136 + seg*17 + col_local] = o0 + o1;

#pragma unroll
            for (int i = 0; i < 8; i++) { kA[i] = kB[i]; qA[i] = qB[i]; }
            vA = vB; fA = fB; gA = gB;
        }
        __syncthreads();

        {
            const int colr = tid & 15, tg = tid >> 4;
#pragma unroll
            for (int rep = 0; rep < 4; rep++) {
                int t = tg + rep*8;
                float s = 0.f;
#pragma unroll
                for (int sg = 0; sg < 8; sg++) s += rs[R_PO + t*136 + sg*17 + colr];
                g_o[basev + (size_t)(tile*RT + t)*DD + qtr*16 + colr] = s;
            }
        }
    }
}

// -------- gate + LayerNorm -> fp16 hi/lo split -------------------------------
__global__ __launch_bounds__(256) void gate_ln_kernel(const float* __restrict__ Wg2,
                                                      const float* __restrict__ nw) {
    __shared__ float g1s[8 * 64];
    __shared__ float rb[8 * 1024];
    const int row0 = blockIdx.x * 8;
    const int tid = threadIdx.x;
    for (int i = tid; i < 512; i += 256) g1s[i] = g_g1[(size_t)row0 * 64 + i];
    __syncthreads();

    float a[8][4];
#pragma unroll
    for (int r = 0; r < 8; r++)
#pragma unroll
        for (int ch = 0; ch < 4; ch++) a[r][ch] = 0.f;

    for (int k4 = 0; k4 < 64; k4 += 4) {
        float4 gr[8];
#pragma unroll
        for (int r = 0; r < 8; r++) gr[r] = *(const float4*)&g1s[r*64 + k4];
#pragma unroll
        for (int ch = 0; ch < 4; ch++) {
            const int c = tid + ch * 256;
            float w0 = Wg2[(size_t)(k4+0)*DD + c];
            float w1 = Wg2[(size_t)(k4+1)*DD + c];
            float w2 = Wg2[(size_t)(k4+2)*DD + c];
            float w3 = Wg2[(size_t)(k4+3)*DD + c];
#pragma unroll
            for (int r = 0; r < 8; r++) {
                float t = fmaf(gr[r].x, w0, fmaf(gr[r].y, w1, fmaf(gr[r].z, w2, gr[r].w * w3)));
                a[r][ch] += t;
            }
        }
    }
#pragma unroll
    for (int ch = 0; ch < 4; ch++) {
        const int c = tid + ch * 256;
#pragma unroll
        for (int r = 0; r < 8; r++)
            rb[r * 1024 + c] = g_o[(size_t)(row0 + r) * DD + c] * sigmoidf_(a[r][ch]);
    }
    __syncthreads();
    const int wr = tid >> 5, ln = tid & 31;
    float s = 0.f, s2 = 0.f;
#pragma unroll 8
    for (int i = 0; i < 32; i++) {
        float v = rb[wr * 1024 + ln + 32 * i];
        s += v; s2 = fmaf(v, v, s2);
    }
#pragma unroll
    for (int o = 16; o; o >>= 1) {
        s  += __shfl_xor_sync(0xffffffffu, s,  o);
        s2 += __shfl_xor_sync(0xffffffffu, s2, o);
    }
    const float mu = s * (1.f / 1024.f);
    const float rstd = rsqrtf(s2 * (1.f / 1024.f) - mu * mu + 1e-5f);
#pragma unroll 8
    for (int i = 0; i < 32; i++) {
        int c = ln + 32 * i;
        float v = (rb[wr * 1024 + c] - mu) * rstd * nw[c];
        __half hi = __float2half_rn(v);
        size_t idx = (size_t)(row0 + wr) * DD + c;
        g_nhi[idx] = hi;
        g_nlo[idx] = __float2half_rn(v - __half2float(hi));
    }
}

// -----------------------------------------------------------------------------
extern "C" void kernel_launch(void* const* d_in, const int* in_sizes, int n_in,
                              void* d_out, int out_size) {
    const float* x      = (const float*)d_in[0];
    const float* Wq     = (const float*)d_in[1];
    const float* Wk     = (const float*)d_in[2];
    const float* Wv     = (const float*)d_in[3];
    const float* Wgamma = (const float*)d_in[4];
    const float* Wf     = (const float*)d_in[5];
    const float* Wg1    = (const float*)d_in[6];
    const float* Wg2    = (const float*)d_in[7];
    const float* Wo     = (const float*)d_in[8];
    const float* norm_w = (const float*)d_in[9];
    float* out = (float*)d_out;

    cudaFuncSetAttribute(gemm_qkv, cudaFuncAttributeMaxDynamicSharedMemorySize, GSMEM);
    cudaFuncSetAttribute(gemm_out, cudaFuncAttributeMaxDynamicSharedMemorySize, GSMEM);
    cudaFuncSetAttribute(recur_kernel, cudaFuncAttributeMaxDynamicSharedMemorySize, RSMEM_BYTES);

    prep_kernel<<<4096 + 4096 + 128, 256>>>(x, Wq, Wk, Wv, Wo, Wgamma, Wf, Wg1);  // 0
    gemm_qkv<<<dim3(25, 32), 128, GSMEM>>>();                                      // 1
    dummy_kernel<<<1, 32>>>();                                                     // 2
    recur_kernel<<<128, 128, RSMEM_BYTES>>>();                                     // 3 <- profiled
    gate_ln_kernel<<<BN/8, 256>>>(Wg2, norm_w);                                    // 4
    gemm_out<<<dim3(8, 32), 128, GSMEM>>>(out);                                    // 5
}